// round 11
// baseline (speedup 1.0000x reference)
#include <cuda_runtime.h>
#include <cuda_bf16.h>
#include <mma.h>
#include <math.h>
#include <cstdint>

using namespace nvcuda;

#define SEQ   2048
#define HID   1024
#define NTOK  1024
#define NHEAD 16
#define HDIM  64

typedef __nv_bfloat16 bf16;

#define PART (3 * SEQ * NTOK)   // stride between split-K partial slabs (floats)

// ---------------- scratch (device globals; no runtime allocation) ----------
__device__ float g_part[2 * 3 * SEQ * NTOK];   // split-K partials (48 MB)
__device__ bf16 g_attnh[3 * SEQ * NTOK];
__device__ bf16 g_attnl[3 * SEQ * NTOK];
__device__ bf16 g_xh[SEQ * HID], g_xl[SEQ * HID];
__device__ bf16 g_ctxh[SEQ * HID], g_ctxl[SEQ * HID];
__device__ bf16 g_wh[8][NTOK * HID];   // qk,qv,kk,kv,vk,vv,pk,pv
__device__ bf16 g_wl[8][NTOK * HID];
__device__ bf16 g_qkvh[3 * SEQ * HID]; // q(scaled),k,v hi
__device__ bf16 g_qkvl[3 * SEQ * HID];

// ---------------- small helpers -------------------------------------------
__device__ __forceinline__ unsigned short b2u(bf16 h) {
    return *reinterpret_cast<unsigned short*>(&h);
}
__device__ __forceinline__ unsigned pb2(bf16 a, bf16 b) {
    return (unsigned)b2u(a) | ((unsigned)b2u(b) << 16);
}
__device__ __forceinline__ void split_bf16(float x, bf16& h, bf16& l) {
    h = __float2bfloat16_rn(x);
    l = __float2bfloat16_rn(x - __bfloat162float(h));
}
__device__ __forceinline__ void cpa16(void* smem, const void* gmem) {
    unsigned s = (unsigned)__cvta_generic_to_shared(smem);
    asm volatile("cp.async.cg.shared.global [%0], [%1], 16;" :: "r"(s), "l"(gmem));
}
#define CPA_COMMIT() asm volatile("cp.async.commit_group;")
#define CPA_WAIT(n)  asm volatile("cp.async.wait_group %0;" :: "n"(n))

// ---------------- conversions ----------------------------------------------
__global__ void __launch_bounds__(256) cvt_hilo(const float* __restrict__ in,
                                                bf16* __restrict__ hi,
                                                bf16* __restrict__ lo)
{
    int i = (blockIdx.x * 256 + threadIdx.x) * 4;
    float4 v = *(const float4*)(in + i);
    bf16 h0, h1, h2, h3, l0, l1, l2, l3;
    split_bf16(v.x, h0, l0); split_bf16(v.y, h1, l1);
    split_bf16(v.z, h2, l2); split_bf16(v.w, h3, l3);
    uint2 H; H.x = pb2(h0, h1); H.y = pb2(h2, h3);
    uint2 L; L.x = pb2(l0, l1); L.y = pb2(l2, l3);
    *(uint2*)(hi + i) = H;
    *(uint2*)(lo + i) = L;
}

struct W8 { const float* src[8]; };

__global__ void __launch_bounds__(256) cvt_hilo8(W8 s,
                                                 bf16* __restrict__ hi,
                                                 bf16* __restrict__ lo)
{
    const size_t WSZ = (size_t)NTOK * HID;
    int z = blockIdx.y;
    int i = (blockIdx.x * 256 + threadIdx.x) * 4;
    float4 v = *(const float4*)(s.src[z] + i);
    bf16 h0, h1, h2, h3, l0, l1, l2, l3;
    split_bf16(v.x, h0, l0); split_bf16(v.y, h1, l1);
    split_bf16(v.z, h2, l2); split_bf16(v.w, h3, l3);
    uint2 H; H.x = pb2(h0, h1); H.y = pb2(h2, h3);
    uint2 L; L.x = pb2(l0, l1); L.y = pb2(l2, l3);
    *(uint2*)(hi + z * WSZ + i) = H;
    *(uint2*)(lo + z * WSZ + i) = L;
}

// split-K partial reduce + scale + bf16 hi/lo split (for q/k/v)
__global__ void __launch_bounds__(256) reduce_cvt_qkv(const float* __restrict__ part,
                                                      bf16* __restrict__ hi,
                                                      bf16* __restrict__ lo)
{
    const size_t SZ = (size_t)SEQ * HID;
    int z = blockIdx.y;
    const float sc = (z == 0) ? 0.125f : 1.f;
    size_t i = (size_t)(blockIdx.x * 256 + threadIdx.x) * 4 + z * SZ;
    float4 a = *(const float4*)(part + i);
    float4 b = *(const float4*)(part + PART + i);
    bf16 h0, h1, h2, h3, l0, l1, l2, l3;
    split_bf16((a.x + b.x) * sc, h0, l0); split_bf16((a.y + b.y) * sc, h1, l1);
    split_bf16((a.z + b.z) * sc, h2, l2); split_bf16((a.w + b.w) * sc, h3, l3);
    uint2 H; H.x = pb2(h0, h1); H.y = pb2(h2, h3);
    uint2 L; L.x = pb2(l0, l1); L.y = pb2(l2, l3);
    *(uint2*)(hi + i) = H;
    *(uint2*)(lo + i) = L;
}

// split-K partial reduce -> fp32 out (final projection)
__global__ void __launch_bounds__(256) reduce_out(const float* __restrict__ part,
                                                  float* __restrict__ out)
{
    size_t i = (size_t)(blockIdx.x * 256 + threadIdx.x) * 4;
    float4 a = *(const float4*)(part + i);
    float4 b = *(const float4*)(part + PART + i);
    *(float4*)(out + i) = make_float4(a.x + b.x, a.y + b.y, a.z + b.z, a.w + b.w);
}

// ---------------- tensor GEMM (bf16 hi/lo, 3 compensated terms, split-K=2) -
//  BT=true : B is [N,K] row-major (C = A*B^T)
//  BT=false: B is [K,N] row-major (C = A*B)
//  128x128 tile, BK=32, 256 threads (8 warps 4x2, warp tile 32x64).
//  Single-sync double-buffered pipeline.
struct GB {
    const bf16 *Ah[3], *Al[3], *Bh[3], *Bl[3];
    float* C[3];
};

#define ASZ 5120                       // 128*40 elems
#define BSZ_BT 5120                    // 128*40 elems
#define BSZ_NBT 4352                   // 32*136 elems
#define GEMM_SMEM_BT  ((4 * ASZ + 4 * BSZ_BT) * 2)    // 81920 bytes
#define GEMM_SMEM_BN  ((4 * ASZ + 4 * BSZ_NBT) * 2)   // 75776 bytes

template <bool BT>
__global__ void __launch_bounds__(256, 2) tgemm_bf16(GB p, int M, int N, int K)
{
    constexpr int BSZ = BT ? BSZ_BT : BSZ_NBT;

    extern __shared__ bf16 dyn[];
    bf16* As_h = dyn;                       // [2][ASZ]
    bf16* As_l = dyn + 2 * ASZ;
    bf16* Bs_h = dyn + 4 * ASZ;             // [2][BSZ]
    bf16* Bs_l = dyn + 4 * ASZ + 2 * BSZ;

    const int zi = blockIdx.z >> 1;
    const int ks = blockIdx.z & 1;
    const bf16* __restrict__ Ah = p.Ah[zi];
    const bf16* __restrict__ Al = p.Al[zi];
    const bf16* __restrict__ Bh = p.Bh[zi];
    const bf16* __restrict__ Bl = p.Bl[zi];
    float* __restrict__ C = p.C[zi] + (size_t)ks * PART;

    const int tid = threadIdx.x;
    const int bx = blockIdx.x;
    const int by = blockIdx.y;
    const int wid = tid >> 5;
    const int wm = wid & 3;
    const int wn = wid >> 2;
    const int kbase = ks * (K / 2);

    wmma::fragment<wmma::accumulator, 16, 16, 16, float> cf[2][4];
#pragma unroll
    for (int mi = 0; mi < 2; mi++)
#pragma unroll
        for (int ni = 0; ni < 4; ni++) wmma::fill_fragment(cf[mi][ni], 0.f);

    int arow[2], akq[2], bkr[2], bnq[2];
#pragma unroll
    for (int i = 0; i < 2; i++) {
        int c = tid + i * 256;
        arow[i] = c >> 2;  akq[i] = (c & 3) * 8;
        if (BT) { bkr[i] = c >> 2;  bnq[i] = (c & 3) * 8; }
        else    { bkr[i] = c >> 4;  bnq[i] = (c & 15) * 8; }
    }

    const int T = K / 64;   // half-K in BK=32 tiles

    auto stage = [&](int t, int b) {
        const int kt = kbase + t * 32;
#pragma unroll
        for (int i = 0; i < 2; i++) {
            cpa16(As_h + b * ASZ + arow[i] * 40 + akq[i],
                  Ah + (size_t)(by * 128 + arow[i]) * K + kt + akq[i]);
            cpa16(As_l + b * ASZ + arow[i] * 40 + akq[i],
                  Al + (size_t)(by * 128 + arow[i]) * K + kt + akq[i]);
            if (BT) {
                cpa16(Bs_h + b * BSZ + bkr[i] * 40 + bnq[i],
                      Bh + (size_t)(bx * 128 + bkr[i]) * K + kt + bnq[i]);
                cpa16(Bs_l + b * BSZ + bkr[i] * 40 + bnq[i],
                      Bl + (size_t)(bx * 128 + bkr[i]) * K + kt + bnq[i]);
            } else {
                cpa16(Bs_h + b * BSZ + bkr[i] * 136 + bnq[i],
                      Bh + (size_t)(kt + bkr[i]) * N + bx * 128 + bnq[i]);
                cpa16(Bs_l + b * BSZ + bkr[i] * 136 + bnq[i],
                      Bl + (size_t)(kt + bkr[i]) * N + bx * 128 + bnq[i]);
            }
        }
        CPA_COMMIT();
    };

    stage(0, 0);

    for (int t = 0; t < T; t++) {
        const int b = t & 1;
        CPA_WAIT(0);                // buffer t landed
        __syncthreads();            // visibility + compute(t-1) done before overwrite
        if (t + 1 < T) stage(t + 1, b ^ 1);   // overlaps compute(t)

        const bf16* ah_p = As_h + b * ASZ;
        const bf16* al_p = As_l + b * ASZ;
        const bf16* bh_p = Bs_h + b * BSZ;
        const bf16* bl_p = Bs_l + b * BSZ;

#pragma unroll
        for (int kk = 0; kk < 2; kk++) {
            wmma::fragment<wmma::matrix_a, 16, 16, 16, bf16,
                           wmma::row_major> ah[2], al[2];
#pragma unroll
            for (int mi = 0; mi < 2; mi++) {
                wmma::load_matrix_sync(ah[mi], ah_p + (wm * 32 + mi * 16) * 40 + kk * 16, 40);
                wmma::load_matrix_sync(al[mi], al_p + (wm * 32 + mi * 16) * 40 + kk * 16, 40);
            }
            if (BT) {
                wmma::fragment<wmma::matrix_b, 16, 16, 16, bf16,
                               wmma::col_major> bh[4], bl[4];
#pragma unroll
                for (int ni = 0; ni < 4; ni++) {
                    wmma::load_matrix_sync(bh[ni], bh_p + (wn * 64 + ni * 16) * 40 + kk * 16, 40);
                    wmma::load_matrix_sync(bl[ni], bl_p + (wn * 64 + ni * 16) * 40 + kk * 16, 40);
                }
#pragma unroll
                for (int mi = 0; mi < 2; mi++)
#pragma unroll
                    for (int ni = 0; ni < 4; ni++) {
                        wmma::mma_sync(cf[mi][ni], ah[mi], bh[ni], cf[mi][ni]);
                        wmma::mma_sync(cf[mi][ni], al[mi], bh[ni], cf[mi][ni]);
                        wmma::mma_sync(cf[mi][ni], ah[mi], bl[ni], cf[mi][ni]);
                    }
            } else {
                wmma::fragment<wmma::matrix_b, 16, 16, 16, bf16,
                               wmma::row_major> bh[4], bl[4];
#pragma unroll
                for (int ni = 0; ni < 4; ni++) {
                    wmma::load_matrix_sync(bh[ni], bh_p + kk * 16 * 136 + wn * 64 + ni * 16, 136);
                    wmma::load_matrix_sync(bl[ni], bl_p + kk * 16 * 136 + wn * 64 + ni * 16, 136);
                }
#pragma unroll
                for (int mi = 0; mi < 2; mi++)
#pragma unroll
                    for (int ni = 0; ni < 4; ni++) {
                        wmma::mma_sync(cf[mi][ni], ah[mi], bh[ni], cf[mi][ni]);
                        wmma::mma_sync(cf[mi][ni], al[mi], bh[ni], cf[mi][ni]);
                        wmma::mma_sync(cf[mi][ni], ah[mi], bl[ni], cf[mi][ni]);
                    }
            }
        }
    }

#pragma unroll
    for (int mi = 0; mi < 2; mi++)
#pragma unroll
        for (int ni = 0; ni < 4; ni++) {
            float* Cp = C + (size_t)(by * 128 + wm * 32 + mi * 16) * N
                          + bx * 128 + wn * 64 + ni * 16;
            wmma::store_matrix_sync(Cp, cf[mi][ni], N, wmma::mem_row_major);
        }
}

// ---------------- gelu + L2-norm over summed split-K partials -------------
__global__ void __launch_bounds__(256) gelu_l2norm_cvt(const float* __restrict__ part,
                                                       bf16* __restrict__ oh,
                                                       bf16* __restrict__ ol)
{
    const int row = blockIdx.x;
    const int tid = threadIdx.x;
    __shared__ float g[NTOK];
    __shared__ float ws[8];

    const float* p0 = part + (size_t)row * NTOK;
    const float* p1 = p0 + PART;

    float ss = 0.f;
    for (int i = tid; i < NTOK; i += 256) {
        float v = p0[i] + p1[i];
        float gv = 0.5f * v * (1.f + erff(v * 0.70710678118654752f));
        g[i] = gv;
        ss += gv * gv;
    }
#pragma unroll
    for (int o = 16; o > 0; o >>= 1) ss += __shfl_xor_sync(0xffffffffu, ss, o);
    if ((tid & 31) == 0) ws[tid >> 5] = ss;
    __syncthreads();

    float tot = 0.f;
#pragma unroll
    for (int w = 0; w < 8; w++) tot += ws[w];

    const float sc = 32.f * rsqrtf(tot);
    for (int i = tid; i < NTOK; i += 256) {
        float v = g[i] * sc;
        bf16 h, l;
        split_bf16(v, h, l);
        oh[(size_t)row * NTOK + i] = h;
        ol[(size_t)row * NTOK + i] = l;
    }
}

// ---------------- tensor-core causal flash attention (wmma) ---------------
// 2-thread/row softmax (m,l in registers), PV accumulates into O via
// load_matrix/store_matrix round-trip, 3 syncs per KV step.
#define FPAD 72
#define SPAD 68

__global__ void __launch_bounds__(256) flash_tc(const bf16* __restrict__ qkvh,
                                                const bf16* __restrict__ qkvl,
                                                bf16* __restrict__ ctxh,
                                                bf16* __restrict__ ctxl)
{
    const size_t SZ = (size_t)SEQ * HID;
    const int tid  = threadIdx.x;
    const int wid  = tid >> 5;
    const int head = blockIdx.y;
    const int qt   = gridDim.x - 1 - blockIdx.x;   // heavy tiles first
    const int hc   = head * HDIM;

    extern __shared__ char dynb[];
    bf16*  Qh  = (bf16*)dynb;
    bf16*  Ql  = Qh + 128 * FPAD;
    bf16*  KVs = Ql + 128 * FPAD;
    float* S   = (float*)(KVs + 2 * 4 * 64 * FPAD);
    float* O   = S + 128 * SPAD;
    bf16*  Ph  = (bf16*)(O + 128 * SPAD);
    bf16*  Pl  = Ph + 128 * FPAD;

    const int myrow  = tid >> 1;      // softmax/epilogue row ownership
    const int myhalf = tid & 1;       // cols myhalf*32 .. +32
    float m_reg = -1e30f, l_reg = 0.f;

    // zero O (each thread zeroes its 32 owned columns)
    {
        float* Orow = O + myrow * SPAD + myhalf * 32;
#pragma unroll
        for (int j = 0; j < 32; j += 4)
            *(float4*)(Orow + j) = make_float4(0.f, 0.f, 0.f, 0.f);
    }

    // stage Q (hi/lo)
    for (int i = tid; i < 1024; i += 256) {
        int r = i >> 3, c8 = (i & 7) * 8;
        size_t g = (size_t)(qt * 128 + r) * HID + hc + c8;
        cpa16(Qh + r * FPAD + c8, qkvh + g);
        cpa16(Ql + r * FPAD + c8, qkvl + g);
    }
    CPA_COMMIT();

    auto stageKV = [&](int step, int buf) {
        const int kb = step * 64;
        bf16* base = KVs + buf * (4 * 64 * FPAD);
        for (int i = tid; i < 512; i += 256) {
            int r = i >> 3, c8 = (i & 7) * 8;
            size_t g = (size_t)(kb + r) * HID + hc + c8;
            cpa16(base + 0 * 64 * FPAD + r * FPAD + c8, qkvh + SZ + g);
            cpa16(base + 1 * 64 * FPAD + r * FPAD + c8, qkvl + SZ + g);
            cpa16(base + 2 * 64 * FPAD + r * FPAD + c8, qkvh + 2 * SZ + g);
            cpa16(base + 3 * 64 * FPAD + r * FPAD + c8, qkvl + 2 * SZ + g);
        }
        CPA_COMMIT();
    };

    const int nsteps = 2 * qt + 2;
    stageKV(0, 0);

    const int wq = wid * 16;

    for (int step = 0; step < nsteps; step++) {
        const int buf = step & 1;
        const int kb  = step * 64;
        CPA_WAIT(0);                 // KV buffer for this step landed
        __syncthreads();             // + prior PV done before overwrite below
        if (step + 1 < nsteps) stageKV(step + 1, buf ^ 1);

        const bf16* kh = KVs + buf * (4 * 64 * FPAD);
        const bf16* kl = kh + 64 * FPAD;
        const bf16* vh = kh + 2 * 64 * FPAD;
        const bf16* vl = kh + 3 * 64 * FPAD;

        // ---- QK^T -> S[128][64] ----
        {
            wmma::fragment<wmma::matrix_a, 16, 16, 16, bf16, wmma::row_major> ah[4], al[4];
#pragma unroll
            for (int ks = 0; ks < 4; ks++) {
                wmma::load_matrix_sync(ah[ks], Qh + wq * FPAD + ks * 16, FPAD);
                wmma::load_matrix_sync(al[ks], Ql + wq * FPAD + ks * 16, FPAD);
            }
#pragma unroll
            for (int nf = 0; nf < 4; nf++) {
                wmma::fragment<wmma::accumulator, 16, 16, 16, float> acc;
                wmma::fill_fragment(acc, 0.f);
#pragma unroll
                for (int ks = 0; ks < 4; ks++) {
                    wmma::fragment<wmma::matrix_b, 16, 16, 16, bf16, wmma::col_major> bh, bl;
                    wmma::load_matrix_sync(bh, kh + nf * 16 * FPAD + ks * 16, FPAD);
                    wmma::load_matrix_sync(bl, kl + nf * 16 * FPAD + ks * 16, FPAD);
                    wmma::mma_sync(acc, ah[ks], bh, acc);
                    wmma::mma_sync(acc, al[ks], bh, acc);
                    wmma::mma_sync(acc, ah[ks], bl, acc);
                }
                wmma::store_matrix_sync(S + wq * SPAD + nf * 16, acc, SPAD,
                                        wmma::mem_row_major);
            }
        }
        __syncthreads();

        // ---- online softmax: 2 threads per row, uniform control flow ----
        {
            const int qrow = qt * 128 + myrow;
            int jmax = qrow - kb + 1;
            if (jmax > 64) jmax = 64;
            const int base = myhalf * 32;
            const float* Srow = S + myrow * SPAD + base;
            unsigned* ph = (unsigned*)(Ph + myrow * FPAD) + myhalf * 16;
            unsigned* pl = (unsigned*)(Pl + myrow * FPAD) + myhalf * 16;

            float lmax = -1e30f;
#pragma unroll
            for (int j = 0; j < 32; j++)
                if (base + j < jmax) lmax = fmaxf(lmax, Srow[j]);
            float omax = __shfl_xor_sync(0xffffffffu, lmax, 1);
            float tmax = fmaxf(lmax, omax);

            const bool active = (jmax > 0);
            float mnew = active ? fmaxf(m_reg, tmax) : m_reg;
            float corr = __expf(m_reg - mnew);   // 1.0 when inactive

            float suml = 0.f;
#pragma unroll
            for (int j2 = 0; j2 < 16; j2++) {
                int ja = base + 2 * j2;
                float pa = (ja < jmax)     ? __expf(Srow[2 * j2]     - mnew) : 0.f;
                float pb = (ja + 1 < jmax) ? __expf(Srow[2 * j2 + 1] - mnew) : 0.f;
                suml += pa + pb;
                bf16 ha, la, hb, lb;
                split_bf16(pa, ha, la); split_bf16(pb, hb, lb);
                ph[j2] = pb2(ha, hb);
                pl[j2] = pb2(la, lb);
            }
            float osum = __shfl_xor_sync(0xffffffffu, suml, 1);
            l_reg = l_reg * corr + suml + osum;
            m_reg = mnew;

            // scale O by corr (fold the rescale into this phase)
            float* Orow = O + myrow * SPAD + base;
#pragma unroll
            for (int j = 0; j < 32; j += 4) {
                float4 v = *(float4*)(Orow + j);
                *(float4*)(Orow + j) = make_float4(v.x * corr, v.y * corr,
                                                   v.z * corr, v.w * corr);
            }
        }
        __syncthreads();

        // ---- P*V accumulated directly into O ----
        {
            wmma::fragment<wmma::matrix_a, 16, 16, 16, bf16, wmma::row_major> pah[4], pal[4];
#pragma unroll
            for (int ks = 0; ks < 4; ks++) {
                wmma::load_matrix_sync(pah[ks], Ph + wq * FPAD + ks * 16, FPAD);
                wmma::load_matrix_sync(pal[ks], Pl + wq * FPAD + ks * 16, FPAD);
            }
#pragma unroll
            for (int nf = 0; nf < 4; nf++) {
                wmma::fragment<wmma::accumulator, 16, 16, 16, float> acc;
                wmma::load_matrix_sync(acc, O + wq * SPAD + nf * 16, SPAD,
                                       wmma::mem_row_major);
#pragma unroll
                for (int ks = 0; ks < 4; ks++) {
                    wmma::fragment<wmma::matrix_b, 16, 16, 16, bf16, wmma::row_major> bh, bl;
                    wmma::load_matrix_sync(bh, vh + ks * 16 * FPAD + nf * 16, FPAD);
                    wmma::load_matrix_sync(bl, vl + ks * 16 * FPAD + nf * 16, FPAD);
                    wmma::mma_sync(acc, pah[ks], bh, acc);
                    wmma::mma_sync(acc, pal[ks], bh, acc);
                    wmma::mma_sync(acc, pah[ks], bl, acc);
                }
                wmma::store_matrix_sync(O + wq * SPAD + nf * 16, acc, SPAD,
                                        wmma::mem_row_major);
            }
        }
    }

    __syncthreads();

    // ---- epilogue: O/l -> ctx hi/lo bf16 (each thread owns 32 cols) ----
    {
        const float invl = 1.f / l_reg;
        const float* Orow = O + myrow * SPAD + myhalf * 32;
        size_t gbase = (size_t)(qt * 128 + myrow) * HID + hc + myhalf * 32;
#pragma unroll
        for (int j = 0; j < 32; j++) {
            float val = Orow[j] * invl;
            bf16 h, l;
            split_bf16(val, h, l);
            ctxh[gbase + j] = h;
            ctxl[gbase + j] = l;
        }
    }
}

#define FLASH_SMEM (2*128*FPAD*2 + 2*4*64*FPAD*2 + 2*128*SPAD*4 + 2*128*FPAD*2 + 128)

// ---------------------------------------------------------------------------
extern "C" void kernel_launch(void* const* d_in, const int* in_sizes, int n_in,
                              void* d_out, int out_size)
{
    const float* x = (const float*)d_in[0];
    float* out = (float*)d_out;

    float* part;
    bf16 *attnh, *attnl, *xh, *xl, *ctxh, *ctxl, *wh, *wl, *qkvh, *qkvl;
    cudaGetSymbolAddress((void**)&part, g_part);
    cudaGetSymbolAddress((void**)&attnh, g_attnh);
    cudaGetSymbolAddress((void**)&attnl, g_attnl);
    cudaGetSymbolAddress((void**)&xh, g_xh);
    cudaGetSymbolAddress((void**)&xl, g_xl);
    cudaGetSymbolAddress((void**)&ctxh, g_ctxh);
    cudaGetSymbolAddress((void**)&ctxl, g_ctxl);
    cudaGetSymbolAddress((void**)&wh, g_wh);
    cudaGetSymbolAddress((void**)&wl, g_wl);
    cudaGetSymbolAddress((void**)&qkvh, g_qkvh);
    cudaGetSymbolAddress((void**)&qkvl, g_qkvl);

    cudaFuncSetAttribute(tgemm_bf16<true>,
                         cudaFuncAttributeMaxDynamicSharedMemorySize, GEMM_SMEM_BT);
    cudaFuncSetAttribute(tgemm_bf16<false>,
                         cudaFuncAttributeMaxDynamicSharedMemorySize, GEMM_SMEM_BN);
    cudaFuncSetAttribute(flash_tc,
                         cudaFuncAttributeMaxDynamicSharedMemorySize, FLASH_SMEM);

    const size_t WSZ = (size_t)NTOK * HID;
    const size_t AS  = (size_t)SEQ * NTOK;
    const size_t SZ  = (size_t)SEQ * HID;

    // convert inputs to bf16 hi/lo
    cvt_hilo<<<SEQ * HID / 1024, 256>>>(x, xh, xl);
    W8 w8;
    for (int i = 0; i < 8; i++) w8.src[i] = (const float*)d_in[1 + i];
    cvt_hilo8<<<dim3(WSZ / 1024, 8), 256>>>(w8, wh, wl);

    dim3 gg3(HID / 128, SEQ / 128, 6);   // 3 z * splitK 2 = 768 CTAs
    dim3 gg1(HID / 128, SEQ / 128, 2);   // 1 z * splitK 2 = 256 CTAs

    // ---- QKV pattention GEMM1 (x @ keys^T), batched over z, split-K=2 ----
    GB p1 = {};
    for (int z = 0; z < 3; z++) {
        p1.Ah[z] = xh;  p1.Al[z] = xl;
        p1.Bh[z] = wh + (size_t)(z * 2) * WSZ;   // qk,kk,vk
        p1.Bl[z] = wl + (size_t)(z * 2) * WSZ;
        p1.C[z]  = part + z * AS;
    }
    tgemm_bf16<true><<<gg3, 256, GEMM_SMEM_BT>>>(p1, SEQ, NTOK, HID);

    gelu_l2norm_cvt<<<3 * SEQ, 256>>>(part, attnh, attnl);

    // ---- GEMM2 (w @ vals), split-K=2 -> partials -> reduce+scale+split ----
    GB p2 = {};
    for (int z = 0; z < 3; z++) {
        p2.Ah[z] = attnh + z * AS;  p2.Al[z] = attnl + z * AS;
        p2.Bh[z] = wh + (size_t)(z * 2 + 1) * WSZ;   // qv,kv,vv
        p2.Bl[z] = wl + (size_t)(z * 2 + 1) * WSZ;
        p2.C[z]  = part + z * SZ;
    }
    tgemm_bf16<false><<<gg3, 256, GEMM_SMEM_BN>>>(p2, SEQ, HID, NTOK);

    reduce_cvt_qkv<<<dim3(SEQ * HID / 1024, 3), 256>>>(part, qkvh, qkvl);

    // ---- tensor-core causal attention -> ctx hi/lo ----
    flash_tc<<<dim3(SEQ / 128, NHEAD), 256, FLASH_SMEM>>>(qkvh, qkvl, ctxh, ctxl);

    // ---- output projection, split-K=2 ----
    GB p3 = {};
    p3.Ah[0] = ctxh; p3.Al[0] = ctxl;
    p3.Bh[0] = wh + (size_t)6 * WSZ;  p3.Bl[0] = wl + (size_t)6 * WSZ;  // pk
    p3.C[0]  = part;
    tgemm_bf16<true><<<gg1, 256, GEMM_SMEM_BT>>>(p3, SEQ, NTOK, HID);

    gelu_l2norm_cvt<<<SEQ, 256>>>(part, attnh, attnl);

    GB p4 = {};
    p4.Ah[0] = attnh; p4.Al[0] = attnl;
    p4.Bh[0] = wh + (size_t)7 * WSZ;  p4.Bl[0] = wl + (size_t)7 * WSZ;  // pv
    p4.C[0]  = part;
    tgemm_bf16<false><<<gg1, 256, GEMM_SMEM_BN>>>(p4, SEQ, HID, NTOK);

    reduce_out<<<SEQ * HID / 1024, 256>>>(part, out);
}

// round 12
// speedup vs baseline: 1.2228x; 1.2228x over previous
#include <cuda_runtime.h>
#include <cuda_bf16.h>
#include <cuda_fp16.h>
#include <mma.h>
#include <math.h>
#include <cstdint>

using namespace nvcuda;

#define SEQ   2048
#define HID   1024
#define NTOK  1024
#define NHEAD 16
#define HDIM  64

typedef __nv_bfloat16 bf16;
typedef __half f16;

#define PART (3 * SEQ * NTOK)   // stride between split-K partial slabs (floats)

// ---------------- scratch (device globals; no runtime allocation) ----------
__device__ float g_part[2 * 3 * SEQ * NTOK];   // split-K partials (48 MB)
__device__ f16 g_attnh[3 * SEQ * NTOK];        // gelu out hi/lo (fp16, GEMM A)
__device__ f16 g_attnl[3 * SEQ * NTOK];
__device__ f16 g_xh[SEQ * HID], g_xl[SEQ * HID];
__device__ f16 g_ctxh[SEQ * HID], g_ctxl[SEQ * HID];
__device__ f16 g_wf[8][NTOK * HID];            // weights, single fp16 (GEMM B)
__device__ bf16 g_qkvh[3 * SEQ * HID];         // flash inputs: bf16 hi/lo
__device__ bf16 g_qkvl[3 * SEQ * HID];

// ---------------- small helpers -------------------------------------------
__device__ __forceinline__ unsigned short b2u(bf16 h) {
    return *reinterpret_cast<unsigned short*>(&h);
}
__device__ __forceinline__ unsigned pb2(bf16 a, bf16 b) {
    return (unsigned)b2u(a) | ((unsigned)b2u(b) << 16);
}
__device__ __forceinline__ void split_bf16(float x, bf16& h, bf16& l) {
    h = __float2bfloat16_rn(x);
    l = __float2bfloat16_rn(x - __bfloat162float(h));
}
__device__ __forceinline__ unsigned short f2u(f16 h) {
    return *reinterpret_cast<unsigned short*>(&h);
}
__device__ __forceinline__ unsigned pf2(f16 a, f16 b) {
    return (unsigned)f2u(a) | ((unsigned)f2u(b) << 16);
}
__device__ __forceinline__ void split_f16(float x, f16& h, f16& l) {
    h = __float2half_rn(x);
    l = __float2half_rn(x - __half2float(h));
}
__device__ __forceinline__ void cpa16(void* smem, const void* gmem) {
    unsigned s = (unsigned)__cvta_generic_to_shared(smem);
    asm volatile("cp.async.cg.shared.global [%0], [%1], 16;" :: "r"(s), "l"(gmem));
}
#define CPA_COMMIT() asm volatile("cp.async.commit_group;")
#define CPA_WAIT(n)  asm volatile("cp.async.wait_group %0;" :: "n"(n))

// ---------------- conversions ----------------------------------------------
// x -> fp16 hi/lo
__global__ void __launch_bounds__(256) cvt_hilo_f16(const float* __restrict__ in,
                                                    f16* __restrict__ hi,
                                                    f16* __restrict__ lo)
{
    int i = (blockIdx.x * 256 + threadIdx.x) * 4;
    float4 v = *(const float4*)(in + i);
    f16 h0, h1, h2, h3, l0, l1, l2, l3;
    split_f16(v.x, h0, l0); split_f16(v.y, h1, l1);
    split_f16(v.z, h2, l2); split_f16(v.w, h3, l3);
    uint2 H; H.x = pf2(h0, h1); H.y = pf2(h2, h3);
    uint2 L; L.x = pf2(l0, l1); L.y = pf2(l2, l3);
    *(uint2*)(hi + i) = H;
    *(uint2*)(lo + i) = L;
}

struct W8 { const float* src[8]; };

// 8 weight matrices -> single fp16
__global__ void __launch_bounds__(256) cvt_w8(W8 s, f16* __restrict__ w)
{
    const size_t WSZ = (size_t)NTOK * HID;
    int z = blockIdx.y;
    int i = (blockIdx.x * 256 + threadIdx.x) * 4;
    float4 v = *(const float4*)(s.src[z] + i);
    uint2 o;
    o.x = pf2(__float2half_rn(v.x), __float2half_rn(v.y));
    o.y = pf2(__float2half_rn(v.z), __float2half_rn(v.w));
    *(uint2*)(w + z * WSZ + i) = o;
}

// split-K partial reduce + scale + bf16 hi/lo split (for flash q/k/v)
__global__ void __launch_bounds__(256) reduce_cvt_qkv(const float* __restrict__ part,
                                                      bf16* __restrict__ hi,
                                                      bf16* __restrict__ lo)
{
    const size_t SZ = (size_t)SEQ * HID;
    int z = blockIdx.y;
    const float sc = (z == 0) ? 0.125f : 1.f;
    size_t i = (size_t)(blockIdx.x * 256 + threadIdx.x) * 4 + z * SZ;
    float4 a = *(const float4*)(part + i);
    float4 b = *(const float4*)(part + PART + i);
    bf16 h0, h1, h2, h3, l0, l1, l2, l3;
    split_bf16((a.x + b.x) * sc, h0, l0); split_bf16((a.y + b.y) * sc, h1, l1);
    split_bf16((a.z + b.z) * sc, h2, l2); split_bf16((a.w + b.w) * sc, h3, l3);
    uint2 H; H.x = pb2(h0, h1); H.y = pb2(h2, h3);
    uint2 L; L.x = pb2(l0, l1); L.y = pb2(l2, l3);
    *(uint2*)(hi + i) = H;
    *(uint2*)(lo + i) = L;
}

// split-K partial reduce -> fp32 out (final projection)
__global__ void __launch_bounds__(256) reduce_out(const float* __restrict__ part,
                                                  float* __restrict__ out)
{
    size_t i = (size_t)(blockIdx.x * 256 + threadIdx.x) * 4;
    float4 a = *(const float4*)(part + i);
    float4 b = *(const float4*)(part + PART + i);
    *(float4*)(out + i) = make_float4(a.x + b.x, a.y + b.y, a.z + b.z, a.w + b.w);
}

// ---------------- tensor GEMM (fp16 A hi/lo x B single, 2 terms, splitK=2) -
//  BT=true : B is [N,K] row-major (C = A*B^T)
//  BT=false: B is [K,N] row-major (C = A*B)
//  128x128 tile, BK=32, 256 threads (8 warps 4x2, warp tile 32x64).
struct GBF {
    const f16 *Ah[3], *Al[3], *B[3];
    float* C[3];
};

#define ASZ 5120                       // 128*40 elems
#define BSZ_BT 5120                    // 128*40 elems
#define BSZ_NBT 4352                   // 32*136 elems
#define GEMM_SMEM_BT  ((4 * ASZ + 2 * BSZ_BT) * 2)    // 61440 bytes
#define GEMM_SMEM_BN  ((4 * ASZ + 2 * BSZ_NBT) * 2)   // 58368 bytes

template <bool BT>
__global__ void __launch_bounds__(256, 2) tgemm_f16(GBF p, int M, int N, int K)
{
    constexpr int BSZ = BT ? BSZ_BT : BSZ_NBT;

    extern __shared__ f16 dyn[];
    f16* As_h = dyn;                       // [2][ASZ]
    f16* As_l = dyn + 2 * ASZ;
    f16* Bs   = dyn + 4 * ASZ;             // [2][BSZ]

    const int zi = blockIdx.z >> 1;
    const int ks = blockIdx.z & 1;
    const f16* __restrict__ Ah = p.Ah[zi];
    const f16* __restrict__ Al = p.Al[zi];
    const f16* __restrict__ B  = p.B[zi];
    float* __restrict__ C = p.C[zi] + (size_t)ks * PART;

    const int tid = threadIdx.x;
    const int bx = blockIdx.x;
    const int by = blockIdx.y;
    const int wid = tid >> 5;
    const int wm = wid & 3;
    const int wn = wid >> 2;
    const int kbase = ks * (K / 2);

    wmma::fragment<wmma::accumulator, 16, 16, 16, float> cf[2][4];
#pragma unroll
    for (int mi = 0; mi < 2; mi++)
#pragma unroll
        for (int ni = 0; ni < 4; ni++) wmma::fill_fragment(cf[mi][ni], 0.f);

    int arow[2], akq[2], bkr[2], bnq[2];
#pragma unroll
    for (int i = 0; i < 2; i++) {
        int c = tid + i * 256;
        arow[i] = c >> 2;  akq[i] = (c & 3) * 8;
        if (BT) { bkr[i] = c >> 2;  bnq[i] = (c & 3) * 8; }
        else    { bkr[i] = c >> 4;  bnq[i] = (c & 15) * 8; }
    }

    const int T = K / 64;   // half-K in BK=32 tiles

    auto stage = [&](int t, int b) {
        const int kt = kbase + t * 32;
#pragma unroll
        for (int i = 0; i < 2; i++) {
            cpa16(As_h + b * ASZ + arow[i] * 40 + akq[i],
                  Ah + (size_t)(by * 128 + arow[i]) * K + kt + akq[i]);
            cpa16(As_l + b * ASZ + arow[i] * 40 + akq[i],
                  Al + (size_t)(by * 128 + arow[i]) * K + kt + akq[i]);
            if (BT) {
                cpa16(Bs + b * BSZ + bkr[i] * 40 + bnq[i],
                      B + (size_t)(bx * 128 + bkr[i]) * K + kt + bnq[i]);
            } else {
                cpa16(Bs + b * BSZ + bkr[i] * 136 + bnq[i],
                      B + (size_t)(kt + bkr[i]) * N + bx * 128 + bnq[i]);
            }
        }
        CPA_COMMIT();
    };

    stage(0, 0);

    for (int t = 0; t < T; t++) {
        const int b = t & 1;
        CPA_WAIT(0);
        __syncthreads();
        if (t + 1 < T) stage(t + 1, b ^ 1);

        const f16* ah_p = As_h + b * ASZ;
        const f16* al_p = As_l + b * ASZ;
        const f16* bs_p = Bs + b * BSZ;

#pragma unroll
        for (int kk = 0; kk < 2; kk++) {
            wmma::fragment<wmma::matrix_a, 16, 16, 16, f16,
                           wmma::row_major> ah[2], al[2];
#pragma unroll
            for (int mi = 0; mi < 2; mi++) {
                wmma::load_matrix_sync(ah[mi], ah_p + (wm * 32 + mi * 16) * 40 + kk * 16, 40);
                wmma::load_matrix_sync(al[mi], al_p + (wm * 32 + mi * 16) * 40 + kk * 16, 40);
            }
            if (BT) {
                wmma::fragment<wmma::matrix_b, 16, 16, 16, f16,
                               wmma::col_major> bfr[4];
#pragma unroll
                for (int ni = 0; ni < 4; ni++)
                    wmma::load_matrix_sync(bfr[ni], bs_p + (wn * 64 + ni * 16) * 40 + kk * 16, 40);
#pragma unroll
                for (int mi = 0; mi < 2; mi++)
#pragma unroll
                    for (int ni = 0; ni < 4; ni++) {
                        wmma::mma_sync(cf[mi][ni], ah[mi], bfr[ni], cf[mi][ni]);
                        wmma::mma_sync(cf[mi][ni], al[mi], bfr[ni], cf[mi][ni]);
                    }
            } else {
                wmma::fragment<wmma::matrix_b, 16, 16, 16, f16,
                               wmma::row_major> bfr[4];
#pragma unroll
                for (int ni = 0; ni < 4; ni++)
                    wmma::load_matrix_sync(bfr[ni], bs_p + kk * 16 * 136 + wn * 64 + ni * 16, 136);
#pragma unroll
                for (int mi = 0; mi < 2; mi++)
#pragma unroll
                    for (int ni = 0; ni < 4; ni++) {
                        wmma::mma_sync(cf[mi][ni], ah[mi], bfr[ni], cf[mi][ni]);
                        wmma::mma_sync(cf[mi][ni], al[mi], bfr[ni], cf[mi][ni]);
                    }
            }
        }
    }

#pragma unroll
    for (int mi = 0; mi < 2; mi++)
#pragma unroll
        for (int ni = 0; ni < 4; ni++) {
            float* Cp = C + (size_t)(by * 128 + wm * 32 + mi * 16) * N
                          + bx * 128 + wn * 64 + ni * 16;
            wmma::store_matrix_sync(Cp, cf[mi][ni], N, wmma::mem_row_major);
        }
}

// ---------------- gelu + L2-norm over summed split-K partials -------------
// outputs fp16 hi/lo (GEMM A operand)
__global__ void __launch_bounds__(256) gelu_l2norm_cvt(const float* __restrict__ part,
                                                       f16* __restrict__ oh,
                                                       f16* __restrict__ ol)
{
    const int row = blockIdx.x;
    const int tid = threadIdx.x;
    __shared__ float g[NTOK];
    __shared__ float ws[8];

    const float* p0 = part + (size_t)row * NTOK;
    const float* p1 = p0 + PART;

    float ss = 0.f;
    for (int i = tid; i < NTOK; i += 256) {
        float v = p0[i] + p1[i];
        float gv = 0.5f * v * (1.f + erff(v * 0.70710678118654752f));
        g[i] = gv;
        ss += gv * gv;
    }
#pragma unroll
    for (int o = 16; o > 0; o >>= 1) ss += __shfl_xor_sync(0xffffffffu, ss, o);
    if ((tid & 31) == 0) ws[tid >> 5] = ss;
    __syncthreads();

    float tot = 0.f;
#pragma unroll
    for (int w = 0; w < 8; w++) tot += ws[w];

    const float sc = 32.f * rsqrtf(tot);
    for (int i = tid; i < NTOK; i += 256) {
        float v = g[i] * sc;
        f16 h, l;
        split_f16(v, h, l);
        oh[(size_t)row * NTOK + i] = h;
        ol[(size_t)row * NTOK + i] = l;
    }
}

// ---------------- tensor-core causal flash attention (wmma, bf16 3-term) --
#define FPAD 72
#define SPAD 68

__global__ void __launch_bounds__(256) flash_tc(const bf16* __restrict__ qkvh,
                                                const bf16* __restrict__ qkvl,
                                                f16* __restrict__ ctxh,
                                                f16* __restrict__ ctxl)
{
    const size_t SZ = (size_t)SEQ * HID;
    const int tid  = threadIdx.x;
    const int wid  = tid >> 5;
    const int head = blockIdx.y;
    const int qt   = gridDim.x - 1 - blockIdx.x;   // heavy tiles first
    const int hc   = head * HDIM;

    extern __shared__ char dynb[];
    bf16*  Qh  = (bf16*)dynb;
    bf16*  Ql  = Qh + 128 * FPAD;
    bf16*  KVs = Ql + 128 * FPAD;
    float* S   = (float*)(KVs + 2 * 4 * 64 * FPAD);
    float* O   = S + 128 * SPAD;
    bf16*  Ph  = (bf16*)(O + 128 * SPAD);
    bf16*  Pl  = Ph + 128 * FPAD;

    const int myrow  = tid >> 1;
    const int myhalf = tid & 1;
    float m_reg = -1e30f, l_reg = 0.f;

    {
        float* Orow = O + myrow * SPAD + myhalf * 32;
#pragma unroll
        for (int j = 0; j < 32; j += 4)
            *(float4*)(Orow + j) = make_float4(0.f, 0.f, 0.f, 0.f);
    }

    for (int i = tid; i < 1024; i += 256) {
        int r = i >> 3, c8 = (i & 7) * 8;
        size_t g = (size_t)(qt * 128 + r) * HID + hc + c8;
        cpa16(Qh + r * FPAD + c8, qkvh + g);
        cpa16(Ql + r * FPAD + c8, qkvl + g);
    }
    CPA_COMMIT();

    auto stageKV = [&](int step, int buf) {
        const int kb = step * 64;
        bf16* base = KVs + buf * (4 * 64 * FPAD);
        for (int i = tid; i < 512; i += 256) {
            int r = i >> 3, c8 = (i & 7) * 8;
            size_t g = (size_t)(kb + r) * HID + hc + c8;
            cpa16(base + 0 * 64 * FPAD + r * FPAD + c8, qkvh + SZ + g);
            cpa16(base + 1 * 64 * FPAD + r * FPAD + c8, qkvl + SZ + g);
            cpa16(base + 2 * 64 * FPAD + r * FPAD + c8, qkvh + 2 * SZ + g);
            cpa16(base + 3 * 64 * FPAD + r * FPAD + c8, qkvl + 2 * SZ + g);
        }
        CPA_COMMIT();
    };

    const int nsteps = 2 * qt + 2;
    stageKV(0, 0);

    const int wq = wid * 16;

    for (int step = 0; step < nsteps; step++) {
        const int buf = step & 1;
        const int kb  = step * 64;
        CPA_WAIT(0);
        __syncthreads();
        if (step + 1 < nsteps) stageKV(step + 1, buf ^ 1);

        const bf16* kh = KVs + buf * (4 * 64 * FPAD);
        const bf16* kl = kh + 64 * FPAD;
        const bf16* vh = kh + 2 * 64 * FPAD;
        const bf16* vl = kh + 3 * 64 * FPAD;

        {
            wmma::fragment<wmma::matrix_a, 16, 16, 16, bf16, wmma::row_major> ah[4], al[4];
#pragma unroll
            for (int ks = 0; ks < 4; ks++) {
                wmma::load_matrix_sync(ah[ks], Qh + wq * FPAD + ks * 16, FPAD);
                wmma::load_matrix_sync(al[ks], Ql + wq * FPAD + ks * 16, FPAD);
            }
#pragma unroll
            for (int nf = 0; nf < 4; nf++) {
                wmma::fragment<wmma::accumulator, 16, 16, 16, float> acc;
                wmma::fill_fragment(acc, 0.f);
#pragma unroll
                for (int ks = 0; ks < 4; ks++) {
                    wmma::fragment<wmma::matrix_b, 16, 16, 16, bf16, wmma::col_major> bh, bl;
                    wmma::load_matrix_sync(bh, kh + nf * 16 * FPAD + ks * 16, FPAD);
                    wmma::load_matrix_sync(bl, kl + nf * 16 * FPAD + ks * 16, FPAD);
                    wmma::mma_sync(acc, ah[ks], bh, acc);
                    wmma::mma_sync(acc, al[ks], bh, acc);
                    wmma::mma_sync(acc, ah[ks], bl, acc);
                }
                wmma::store_matrix_sync(S + wq * SPAD + nf * 16, acc, SPAD,
                                        wmma::mem_row_major);
            }
        }
        __syncthreads();

        {
            const int qrow = qt * 128 + myrow;
            int jmax = qrow - kb + 1;
            if (jmax > 64) jmax = 64;
            const int base = myhalf * 32;
            const float* Srow = S + myrow * SPAD + base;
            unsigned* ph = (unsigned*)(Ph + myrow * FPAD) + myhalf * 16;
            unsigned* pl = (unsigned*)(Pl + myrow * FPAD) + myhalf * 16;

            float lmax = -1e30f;
#pragma unroll
            for (int j = 0; j < 32; j++)
                if (base + j < jmax) lmax = fmaxf(lmax, Srow[j]);
            float omax = __shfl_xor_sync(0xffffffffu, lmax, 1);
            float tmax = fmaxf(lmax, omax);

            const bool active = (jmax > 0);
            float mnew = active ? fmaxf(m_reg, tmax) : m_reg;
            float corr = __expf(m_reg - mnew);

            float suml = 0.f;
#pragma unroll
            for (int j2 = 0; j2 < 16; j2++) {
                int ja = base + 2 * j2;
                float pa = (ja < jmax)     ? __expf(Srow[2 * j2]     - mnew) : 0.f;
                float pb = (ja + 1 < jmax) ? __expf(Srow[2 * j2 + 1] - mnew) : 0.f;
                suml += pa + pb;
                bf16 ha, la, hb, lb;
                split_bf16(pa, ha, la); split_bf16(pb, hb, lb);
                ph[j2] = pb2(ha, hb);
                pl[j2] = pb2(la, lb);
            }
            float osum = __shfl_xor_sync(0xffffffffu, suml, 1);
            l_reg = l_reg * corr + suml + osum;
            m_reg = mnew;

            float* Orow = O + myrow * SPAD + base;
#pragma unroll
            for (int j = 0; j < 32; j += 4) {
                float4 v = *(float4*)(Orow + j);
                *(float4*)(Orow + j) = make_float4(v.x * corr, v.y * corr,
                                                   v.z * corr, v.w * corr);
            }
        }
        __syncthreads();

        {
            wmma::fragment<wmma::matrix_a, 16, 16, 16, bf16, wmma::row_major> pah[4], pal[4];
#pragma unroll
            for (int ks = 0; ks < 4; ks++) {
                wmma::load_matrix_sync(pah[ks], Ph + wq * FPAD + ks * 16, FPAD);
                wmma::load_matrix_sync(pal[ks], Pl + wq * FPAD + ks * 16, FPAD);
            }
#pragma unroll
            for (int nf = 0; nf < 4; nf++) {
                wmma::fragment<wmma::accumulator, 16, 16, 16, float> acc;
                wmma::load_matrix_sync(acc, O + wq * SPAD + nf * 16, SPAD,
                                       wmma::mem_row_major);
#pragma unroll
                for (int ks = 0; ks < 4; ks++) {
                    wmma::fragment<wmma::matrix_b, 16, 16, 16, bf16, wmma::row_major> bh, bl;
                    wmma::load_matrix_sync(bh, vh + ks * 16 * FPAD + nf * 16, FPAD);
                    wmma::load_matrix_sync(bl, vl + ks * 16 * FPAD + nf * 16, FPAD);
                    wmma::mma_sync(acc, pah[ks], bh, acc);
                    wmma::mma_sync(acc, pal[ks], bh, acc);
                    wmma::mma_sync(acc, pah[ks], bl, acc);
                }
                wmma::store_matrix_sync(O + wq * SPAD + nf * 16, acc, SPAD,
                                        wmma::mem_row_major);
            }
        }
    }

    __syncthreads();

    // epilogue: O/l -> ctx fp16 hi/lo
    {
        const float invl = 1.f / l_reg;
        const float* Orow = O + myrow * SPAD + myhalf * 32;
        size_t gbase = (size_t)(qt * 128 + myrow) * HID + hc + myhalf * 32;
#pragma unroll
        for (int j = 0; j < 32; j++) {
            float val = Orow[j] * invl;
            f16 h, l;
            split_f16(val, h, l);
            ctxh[gbase + j] = h;
            ctxl[gbase + j] = l;
        }
    }
}

#define FLASH_SMEM (2*128*FPAD*2 + 2*4*64*FPAD*2 + 2*128*SPAD*4 + 2*128*FPAD*2 + 128)

// ---------------------------------------------------------------------------
extern "C" void kernel_launch(void* const* d_in, const int* in_sizes, int n_in,
                              void* d_out, int out_size)
{
    const float* x = (const float*)d_in[0];
    float* out = (float*)d_out;

    float* part;
    f16 *attnh, *attnl, *xh, *xl, *ctxh, *ctxl, *wf;
    bf16 *qkvh, *qkvl;
    cudaGetSymbolAddress((void**)&part, g_part);
    cudaGetSymbolAddress((void**)&attnh, g_attnh);
    cudaGetSymbolAddress((void**)&attnl, g_attnl);
    cudaGetSymbolAddress((void**)&xh, g_xh);
    cudaGetSymbolAddress((void**)&xl, g_xl);
    cudaGetSymbolAddress((void**)&ctxh, g_ctxh);
    cudaGetSymbolAddress((void**)&ctxl, g_ctxl);
    cudaGetSymbolAddress((void**)&wf, g_wf);
    cudaGetSymbolAddress((void**)&qkvh, g_qkvh);
    cudaGetSymbolAddress((void**)&qkvl, g_qkvl);

    cudaFuncSetAttribute(tgemm_f16<true>,
                         cudaFuncAttributeMaxDynamicSharedMemorySize, GEMM_SMEM_BT);
    cudaFuncSetAttribute(tgemm_f16<false>,
                         cudaFuncAttributeMaxDynamicSharedMemorySize, GEMM_SMEM_BN);
    cudaFuncSetAttribute(flash_tc,
                         cudaFuncAttributeMaxDynamicSharedMemorySize, FLASH_SMEM);

    const size_t WSZ = (size_t)NTOK * HID;
    const size_t AS  = (size_t)SEQ * NTOK;
    const size_t SZ  = (size_t)SEQ * HID;

    // convert inputs
    cvt_hilo_f16<<<SEQ * HID / 1024, 256>>>(x, xh, xl);
    W8 w8;
    for (int i = 0; i < 8; i++) w8.src[i] = (const float*)d_in[1 + i];
    cvt_w8<<<dim3(WSZ / 1024, 8), 256>>>(w8, wf);

    dim3 gg3(HID / 128, SEQ / 128, 6);   // 3 z * splitK 2
    dim3 gg1(HID / 128, SEQ / 128, 2);   // 1 z * splitK 2

    // ---- QKV pattention GEMM1 (x @ keys^T), batched, split-K=2 ----
    GBF p1 = {};
    for (int z = 0; z < 3; z++) {
        p1.Ah[z] = xh;  p1.Al[z] = xl;
        p1.B[z]  = wf + (size_t)(z * 2) * WSZ;   // qk,kk,vk
        p1.C[z]  = part + z * AS;
    }
    tgemm_f16<true><<<gg3, 256, GEMM_SMEM_BT>>>(p1, SEQ, NTOK, HID);

    gelu_l2norm_cvt<<<3 * SEQ, 256>>>(part, attnh, attnl);

    // ---- GEMM2 (w @ vals), split-K=2 -> reduce+scale+split to bf16 ----
    GBF p2 = {};
    for (int z = 0; z < 3; z++) {
        p2.Ah[z] = attnh + z * AS;  p2.Al[z] = attnl + z * AS;
        p2.B[z]  = wf + (size_t)(z * 2 + 1) * WSZ;   // qv,kv,vv
        p2.C[z]  = part + z * SZ;
    }
    tgemm_f16<false><<<gg3, 256, GEMM_SMEM_BN>>>(p2, SEQ, HID, NTOK);

    reduce_cvt_qkv<<<dim3(SEQ * HID / 1024, 3), 256>>>(part, qkvh, qkvl);

    // ---- tensor-core causal attention (bf16 3-term) -> ctx fp16 hi/lo ----
    flash_tc<<<dim3(SEQ / 128, NHEAD), 256, FLASH_SMEM>>>(qkvh, qkvl, ctxh, ctxl);

    // ---- output projection, split-K=2 ----
    GBF p3 = {};
    p3.Ah[0] = ctxh; p3.Al[0] = ctxl;
    p3.B[0]  = wf + (size_t)6 * WSZ;   // pk
    p3.C[0]  = part;
    tgemm_f16<true><<<gg1, 256, GEMM_SMEM_BT>>>(p3, SEQ, NTOK, HID);

    gelu_l2norm_cvt<<<SEQ, 256>>>(part, attnh, attnl);

    GBF p4 = {};
    p4.Ah[0] = attnh; p4.Al[0] = attnl;
    p4.B[0]  = wf + (size_t)7 * WSZ;   // pv
    p4.C[0]  = part;
    tgemm_f16<false><<<gg1, 256, GEMM_SMEM_BN>>>(p4, SEQ, HID, NTOK);

    reduce_out<<<SEQ * HID / 1024, 256>>>(part, out);
}

// round 13
// speedup vs baseline: 1.4569x; 1.1914x over previous
#include <cuda_runtime.h>
#include <cuda_bf16.h>
#include <cuda_fp16.h>
#include <mma.h>
#include <math.h>
#include <cstdint>

using namespace nvcuda;

#define SEQ   2048
#define HID   1024
#define NTOK  1024
#define NHEAD 16
#define HDIM  64

typedef __half f16;

#define PART (3 * SEQ * NTOK)   // stride between split-K partial slabs (floats)

// ---------------- scratch (device globals; no runtime allocation) ----------
__device__ float g_part[2 * 3 * SEQ * NTOK];   // split-K partials (48 MB)
__device__ f16 g_attnh[3 * SEQ * NTOK];        // gelu out hi/lo (fp16, GEMM A)
__device__ f16 g_attnl[3 * SEQ * NTOK];
__device__ f16 g_xh[SEQ * HID], g_xl[SEQ * HID];
__device__ f16 g_ctxh[SEQ * HID], g_ctxl[SEQ * HID];
__device__ f16 g_wf[8][NTOK * HID];            // weights, single fp16 (GEMM B)
__device__ f16 g_qkvh[3 * SEQ * HID];          // q hi (scaled) | k | v
__device__ f16 g_qkvl[3 * SEQ * HID];          // q lo          | (unused)

// ---------------- small helpers -------------------------------------------
__device__ __forceinline__ unsigned short f2u(f16 h) {
    return *reinterpret_cast<unsigned short*>(&h);
}
__device__ __forceinline__ unsigned pf2(f16 a, f16 b) {
    return (unsigned)f2u(a) | ((unsigned)f2u(b) << 16);
}
__device__ __forceinline__ void split_f16(float x, f16& h, f16& l) {
    h = __float2half_rn(x);
    l = __float2half_rn(x - __half2float(h));
}
__device__ __forceinline__ void cpa16(void* smem, const void* gmem) {
    unsigned s = (unsigned)__cvta_generic_to_shared(smem);
    asm volatile("cp.async.cg.shared.global [%0], [%1], 16;" :: "r"(s), "l"(gmem));
}
#define CPA_COMMIT() asm volatile("cp.async.commit_group;")
#define CPA_WAIT(n)  asm volatile("cp.async.wait_group %0;" :: "n"(n))

// ---------------- conversions ----------------------------------------------
__global__ void __launch_bounds__(256) cvt_hilo_f16(const float* __restrict__ in,
                                                    f16* __restrict__ hi,
                                                    f16* __restrict__ lo)
{
    int i = (blockIdx.x * 256 + threadIdx.x) * 4;
    float4 v = *(const float4*)(in + i);
    f16 h0, h1, h2, h3, l0, l1, l2, l3;
    split_f16(v.x, h0, l0); split_f16(v.y, h1, l1);
    split_f16(v.z, h2, l2); split_f16(v.w, h3, l3);
    uint2 H; H.x = pf2(h0, h1); H.y = pf2(h2, h3);
    uint2 L; L.x = pf2(l0, l1); L.y = pf2(l2, l3);
    *(uint2*)(hi + i) = H;
    *(uint2*)(lo + i) = L;
}

struct W8 { const float* src[8]; };

__global__ void __launch_bounds__(256) cvt_w8(W8 s, f16* __restrict__ w)
{
    const size_t WSZ = (size_t)NTOK * HID;
    int z = blockIdx.y;
    int i = (blockIdx.x * 256 + threadIdx.x) * 4;
    float4 v = *(const float4*)(s.src[z] + i);
    uint2 o;
    o.x = pf2(__float2half_rn(v.x), __float2half_rn(v.y));
    o.y = pf2(__float2half_rn(v.z), __float2half_rn(v.w));
    *(uint2*)(w + z * WSZ + i) = o;
}

// split-K partial reduce + scale + fp16 hi/lo split (for flash q/k/v)
__global__ void __launch_bounds__(256) reduce_cvt_qkv(const float* __restrict__ part,
                                                      f16* __restrict__ hi,
                                                      f16* __restrict__ lo)
{
    const size_t SZ = (size_t)SEQ * HID;
    int z = blockIdx.y;
    const float sc = (z == 0) ? 0.125f : 1.f;
    size_t i = (size_t)(blockIdx.x * 256 + threadIdx.x) * 4 + z * SZ;
    float4 a = *(const float4*)(part + i);
    float4 b = *(const float4*)(part + PART + i);
    f16 h0, h1, h2, h3, l0, l1, l2, l3;
    split_f16((a.x + b.x) * sc, h0, l0); split_f16((a.y + b.y) * sc, h1, l1);
    split_f16((a.z + b.z) * sc, h2, l2); split_f16((a.w + b.w) * sc, h3, l3);
    uint2 H; H.x = pf2(h0, h1); H.y = pf2(h2, h3);
    uint2 L; L.x = pf2(l0, l1); L.y = pf2(l2, l3);
    *(uint2*)(hi + i) = H;
    *(uint2*)(lo + i) = L;
}

// split-K partial reduce -> fp32 out (final projection)
__global__ void __launch_bounds__(256) reduce_out(const float* __restrict__ part,
                                                  float* __restrict__ out)
{
    size_t i = (size_t)(blockIdx.x * 256 + threadIdx.x) * 4;
    float4 a = *(const float4*)(part + i);
    float4 b = *(const float4*)(part + PART + i);
    *(float4*)(out + i) = make_float4(a.x + b.x, a.y + b.y, a.z + b.z, a.w + b.w);
}

// ---------------- tensor GEMM (fp16 A hi/lo x B single, 2 terms, splitK=2) -
struct GBF {
    const f16 *Ah[3], *Al[3], *B[3];
    float* C[3];
};

#define ASZ 5120                       // 128*40 elems
#define BSZ_BT 5120                    // 128*40 elems
#define BSZ_NBT 4352                   // 32*136 elems
#define GEMM_SMEM_BT  ((4 * ASZ + 2 * BSZ_BT) * 2)    // 61440 bytes
#define GEMM_SMEM_BN  ((4 * ASZ + 2 * BSZ_NBT) * 2)   // 58368 bytes

template <bool BT>
__global__ void __launch_bounds__(256, 2) tgemm_f16(GBF p, int M, int N, int K)
{
    constexpr int BSZ = BT ? BSZ_BT : BSZ_NBT;

    extern __shared__ f16 dyn[];
    f16* As_h = dyn;                       // [2][ASZ]
    f16* As_l = dyn + 2 * ASZ;
    f16* Bs   = dyn + 4 * ASZ;             // [2][BSZ]

    const int zi = blockIdx.z >> 1;
    const int ks = blockIdx.z & 1;
    const f16* __restrict__ Ah = p.Ah[zi];
    const f16* __restrict__ Al = p.Al[zi];
    const f16* __restrict__ B  = p.B[zi];
    float* __restrict__ C = p.C[zi] + (size_t)ks * PART;

    const int tid = threadIdx.x;
    const int bx = blockIdx.x;
    const int by = blockIdx.y;
    const int wid = tid >> 5;
    const int wm = wid & 3;
    const int wn = wid >> 2;
    const int kbase = ks * (K / 2);

    wmma::fragment<wmma::accumulator, 16, 16, 16, float> cf[2][4];
#pragma unroll
    for (int mi = 0; mi < 2; mi++)
#pragma unroll
        for (int ni = 0; ni < 4; ni++) wmma::fill_fragment(cf[mi][ni], 0.f);

    int arow[2], akq[2], bkr[2], bnq[2];
#pragma unroll
    for (int i = 0; i < 2; i++) {
        int c = tid + i * 256;
        arow[i] = c >> 2;  akq[i] = (c & 3) * 8;
        if (BT) { bkr[i] = c >> 2;  bnq[i] = (c & 3) * 8; }
        else    { bkr[i] = c >> 4;  bnq[i] = (c & 15) * 8; }
    }

    const int T = K / 64;   // half-K in BK=32 tiles

    auto stage = [&](int t, int b) {
        const int kt = kbase + t * 32;
#pragma unroll
        for (int i = 0; i < 2; i++) {
            cpa16(As_h + b * ASZ + arow[i] * 40 + akq[i],
                  Ah + (size_t)(by * 128 + arow[i]) * K + kt + akq[i]);
            cpa16(As_l + b * ASZ + arow[i] * 40 + akq[i],
                  Al + (size_t)(by * 128 + arow[i]) * K + kt + akq[i]);
            if (BT) {
                cpa16(Bs + b * BSZ + bkr[i] * 40 + bnq[i],
                      B + (size_t)(bx * 128 + bkr[i]) * K + kt + bnq[i]);
            } else {
                cpa16(Bs + b * BSZ + bkr[i] * 136 + bnq[i],
                      B + (size_t)(kt + bkr[i]) * N + bx * 128 + bnq[i]);
            }
        }
        CPA_COMMIT();
    };

    stage(0, 0);

    for (int t = 0; t < T; t++) {
        const int b = t & 1;
        CPA_WAIT(0);
        __syncthreads();
        if (t + 1 < T) stage(t + 1, b ^ 1);

        const f16* ah_p = As_h + b * ASZ;
        const f16* al_p = As_l + b * ASZ;
        const f16* bs_p = Bs + b * BSZ;

#pragma unroll
        for (int kk = 0; kk < 2; kk++) {
            wmma::fragment<wmma::matrix_a, 16, 16, 16, f16,
                           wmma::row_major> ah[2], al[2];
#pragma unroll
            for (int mi = 0; mi < 2; mi++) {
                wmma::load_matrix_sync(ah[mi], ah_p + (wm * 32 + mi * 16) * 40 + kk * 16, 40);
                wmma::load_matrix_sync(al[mi], al_p + (wm * 32 + mi * 16) * 40 + kk * 16, 40);
            }
            if (BT) {
                wmma::fragment<wmma::matrix_b, 16, 16, 16, f16,
                               wmma::col_major> bfr[4];
#pragma unroll
                for (int ni = 0; ni < 4; ni++)
                    wmma::load_matrix_sync(bfr[ni], bs_p + (wn * 64 + ni * 16) * 40 + kk * 16, 40);
#pragma unroll
                for (int mi = 0; mi < 2; mi++)
#pragma unroll
                    for (int ni = 0; ni < 4; ni++) {
                        wmma::mma_sync(cf[mi][ni], ah[mi], bfr[ni], cf[mi][ni]);
                        wmma::mma_sync(cf[mi][ni], al[mi], bfr[ni], cf[mi][ni]);
                    }
            } else {
                wmma::fragment<wmma::matrix_b, 16, 16, 16, f16,
                               wmma::row_major> bfr[4];
#pragma unroll
                for (int ni = 0; ni < 4; ni++)
                    wmma::load_matrix_sync(bfr[ni], bs_p + kk * 16 * 136 + wn * 64 + ni * 16, 136);
#pragma unroll
                for (int mi = 0; mi < 2; mi++)
#pragma unroll
                    for (int ni = 0; ni < 4; ni++) {
                        wmma::mma_sync(cf[mi][ni], ah[mi], bfr[ni], cf[mi][ni]);
                        wmma::mma_sync(cf[mi][ni], al[mi], bfr[ni], cf[mi][ni]);
                    }
            }
        }
    }

#pragma unroll
    for (int mi = 0; mi < 2; mi++)
#pragma unroll
        for (int ni = 0; ni < 4; ni++) {
            float* Cp = C + (size_t)(by * 128 + wm * 32 + mi * 16) * N
                          + bx * 128 + wn * 64 + ni * 16;
            wmma::store_matrix_sync(Cp, cf[mi][ni], N, wmma::mem_row_major);
        }
}

// ---------------- gelu + L2-norm over summed split-K partials -------------
__global__ void __launch_bounds__(256) gelu_l2norm_cvt(const float* __restrict__ part,
                                                       f16* __restrict__ oh,
                                                       f16* __restrict__ ol)
{
    const int row = blockIdx.x;
    const int tid = threadIdx.x;
    __shared__ float g[NTOK];
    __shared__ float ws[8];

    const float* p0 = part + (size_t)row * NTOK;
    const float* p1 = p0 + PART;

    float ss = 0.f;
    for (int i = tid; i < NTOK; i += 256) {
        float v = p0[i] + p1[i];
        float gv = 0.5f * v * (1.f + erff(v * 0.70710678118654752f));
        g[i] = gv;
        ss += gv * gv;
    }
#pragma unroll
    for (int o = 16; o > 0; o >>= 1) ss += __shfl_xor_sync(0xffffffffu, ss, o);
    if ((tid & 31) == 0) ws[tid >> 5] = ss;
    __syncthreads();

    float tot = 0.f;
#pragma unroll
    for (int w = 0; w < 8; w++) tot += ws[w];

    const float sc = 32.f * rsqrtf(tot);
    for (int i = tid; i < NTOK; i += 256) {
        float v = g[i] * sc;
        f16 h, l;
        split_f16(v, h, l);
        oh[(size_t)row * NTOK + i] = h;
        ol[(size_t)row * NTOK + i] = l;
    }
}

// ---------------- tensor-core causal flash attention (fp16, 2-term) -------
// Q hi/lo fp16 (exact), K/V single fp16. QK = 2 mma, PV = 2 mma.
#define FPAD 72
#define SPAD 68

__global__ void __launch_bounds__(256) flash_tc(const f16* __restrict__ qkvh,
                                                const f16* __restrict__ qkvl,
                                                f16* __restrict__ ctxh,
                                                f16* __restrict__ ctxl)
{
    const size_t SZ = (size_t)SEQ * HID;
    const int tid  = threadIdx.x;
    const int wid  = tid >> 5;
    const int head = blockIdx.y;
    const int qt   = gridDim.x - 1 - blockIdx.x;   // heavy tiles first
    const int hc   = head * HDIM;

    extern __shared__ char dynb[];
    f16*   Qh  = (f16*)dynb;                        // [128][72]
    f16*   Ql  = Qh + 128 * FPAD;
    f16*   KVs = Ql + 128 * FPAD;                   // [2 buf][2 arr][64*72]
    float* S   = (float*)(KVs + 2 * 2 * 64 * FPAD); // [128][68]
    float* O   = S + 128 * SPAD;                    // [128][68]
    f16*   Ph  = (f16*)(O + 128 * SPAD);            // [128][72]
    f16*   Pl  = Ph + 128 * FPAD;

    const int myrow  = tid >> 1;
    const int myhalf = tid & 1;
    float m_reg = -1e30f, l_reg = 0.f;

    {
        float* Orow = O + myrow * SPAD + myhalf * 32;
#pragma unroll
        for (int j = 0; j < 32; j += 4)
            *(float4*)(Orow + j) = make_float4(0.f, 0.f, 0.f, 0.f);
    }

    for (int i = tid; i < 1024; i += 256) {
        int r = i >> 3, c8 = (i & 7) * 8;
        size_t g = (size_t)(qt * 128 + r) * HID + hc + c8;
        cpa16(Qh + r * FPAD + c8, qkvh + g);
        cpa16(Ql + r * FPAD + c8, qkvl + g);
    }
    CPA_COMMIT();

    auto stageKV = [&](int step, int buf) {
        const int kb = step * 64;
        f16* base = KVs + buf * (2 * 64 * FPAD);
        for (int i = tid; i < 512; i += 256) {
            int r = i >> 3, c8 = (i & 7) * 8;
            size_t g = (size_t)(kb + r) * HID + hc + c8;
            cpa16(base + 0 * 64 * FPAD + r * FPAD + c8, qkvh + SZ + g);       // K
            cpa16(base + 1 * 64 * FPAD + r * FPAD + c8, qkvh + 2 * SZ + g);   // V
        }
        CPA_COMMIT();
    };

    const int nsteps = 2 * qt + 2;
    stageKV(0, 0);

    const int wq = wid * 16;

    for (int step = 0; step < nsteps; step++) {
        const int buf = step & 1;
        const int kb  = step * 64;
        CPA_WAIT(0);
        __syncthreads();
        if (step + 1 < nsteps) stageKV(step + 1, buf ^ 1);

        const f16* kf = KVs + buf * (2 * 64 * FPAD);
        const f16* vf = kf + 64 * FPAD;

        // ---- QK^T -> S[128][64] (2-term) ----
        {
            wmma::fragment<wmma::matrix_a, 16, 16, 16, f16, wmma::row_major> ah[4], al[4];
#pragma unroll
            for (int ks = 0; ks < 4; ks++) {
                wmma::load_matrix_sync(ah[ks], Qh + wq * FPAD + ks * 16, FPAD);
                wmma::load_matrix_sync(al[ks], Ql + wq * FPAD + ks * 16, FPAD);
            }
#pragma unroll
            for (int nf = 0; nf < 4; nf++) {
                wmma::fragment<wmma::accumulator, 16, 16, 16, float> acc;
                wmma::fill_fragment(acc, 0.f);
#pragma unroll
                for (int ks = 0; ks < 4; ks++) {
                    wmma::fragment<wmma::matrix_b, 16, 16, 16, f16, wmma::col_major> bk;
                    wmma::load_matrix_sync(bk, kf + nf * 16 * FPAD + ks * 16, FPAD);
                    wmma::mma_sync(acc, ah[ks], bk, acc);
                    wmma::mma_sync(acc, al[ks], bk, acc);
                }
                wmma::store_matrix_sync(S + wq * SPAD + nf * 16, acc, SPAD,
                                        wmma::mem_row_major);
            }
        }
        __syncthreads();

        // ---- online softmax: 2 threads per row ----
        {
            const int qrow = qt * 128 + myrow;
            int jmax = qrow - kb + 1;
            if (jmax > 64) jmax = 64;
            const int base = myhalf * 32;
            const float* Srow = S + myrow * SPAD + base;
            unsigned* ph = (unsigned*)(Ph + myrow * FPAD) + myhalf * 16;
            unsigned* pl = (unsigned*)(Pl + myrow * FPAD) + myhalf * 16;

            float lmax = -1e30f;
#pragma unroll
            for (int j = 0; j < 32; j++)
                if (base + j < jmax) lmax = fmaxf(lmax, Srow[j]);
            float omax = __shfl_xor_sync(0xffffffffu, lmax, 1);
            float tmax = fmaxf(lmax, omax);

            const bool active = (jmax > 0);
            float mnew = active ? fmaxf(m_reg, tmax) : m_reg;
            float corr = __expf(m_reg - mnew);

            float suml = 0.f;
#pragma unroll
            for (int j2 = 0; j2 < 16; j2++) {
                int ja = base + 2 * j2;
                float pa = (ja < jmax)     ? __expf(Srow[2 * j2]     - mnew) : 0.f;
                float pb = (ja + 1 < jmax) ? __expf(Srow[2 * j2 + 1] - mnew) : 0.f;
                suml += pa + pb;
                f16 ha, la, hb, lb;
                split_f16(pa, ha, la); split_f16(pb, hb, lb);
                ph[j2] = pf2(ha, hb);
                pl[j2] = pf2(la, lb);
            }
            float osum = __shfl_xor_sync(0xffffffffu, suml, 1);
            l_reg = l_reg * corr + suml + osum;
            m_reg = mnew;

            float* Orow = O + myrow * SPAD + base;
#pragma unroll
            for (int j = 0; j < 32; j += 4) {
                float4 v = *(float4*)(Orow + j);
                *(float4*)(Orow + j) = make_float4(v.x * corr, v.y * corr,
                                                   v.z * corr, v.w * corr);
            }
        }
        __syncthreads();

        // ---- P*V accumulated into O (2-term) ----
        {
            wmma::fragment<wmma::matrix_a, 16, 16, 16, f16, wmma::row_major> pah[4], pal[4];
#pragma unroll
            for (int ks = 0; ks < 4; ks++) {
                wmma::load_matrix_sync(pah[ks], Ph + wq * FPAD + ks * 16, FPAD);
                wmma::load_matrix_sync(pal[ks], Pl + wq * FPAD + ks * 16, FPAD);
            }
#pragma unroll
            for (int nf = 0; nf < 4; nf++) {
                wmma::fragment<wmma::accumulator, 16, 16, 16, float> acc;
                wmma::load_matrix_sync(acc, O + wq * SPAD + nf * 16, SPAD,
                                       wmma::mem_row_major);
#pragma unroll
                for (int ks = 0; ks < 4; ks++) {
                    wmma::fragment<wmma::matrix_b, 16, 16, 16, f16, wmma::row_major> bv;
                    wmma::load_matrix_sync(bv, vf + ks * 16 * FPAD + nf * 16, FPAD);
                    wmma::mma_sync(acc, pah[ks], bv, acc);
                    wmma::mma_sync(acc, pal[ks], bv, acc);
                }
                wmma::store_matrix_sync(O + wq * SPAD + nf * 16, acc, SPAD,
                                        wmma::mem_row_major);
            }
        }
    }

    __syncthreads();

    // epilogue: O/l -> ctx fp16 hi/lo
    {
        const float invl = 1.f / l_reg;
        const float* Orow = O + myrow * SPAD + myhalf * 32;
        size_t gbase = (size_t)(qt * 128 + myrow) * HID + hc + myhalf * 32;
#pragma unroll
        for (int j = 0; j < 32; j++) {
            float val = Orow[j] * invl;
            f16 h, l;
            split_f16(val, h, l);
            ctxh[gbase + j] = h;
            ctxl[gbase + j] = l;
        }
    }
}

#define FLASH_SMEM (2*128*FPAD*2 + 2*2*64*FPAD*2 + 2*128*SPAD*4 + 2*128*FPAD*2 + 128)

// ---------------------------------------------------------------------------
extern "C" void kernel_launch(void* const* d_in, const int* in_sizes, int n_in,
                              void* d_out, int out_size)
{
    const float* x = (const float*)d_in[0];
    float* out = (float*)d_out;

    float* part;
    f16 *attnh, *attnl, *xh, *xl, *ctxh, *ctxl, *wf, *qkvh, *qkvl;
    cudaGetSymbolAddress((void**)&part, g_part);
    cudaGetSymbolAddress((void**)&attnh, g_attnh);
    cudaGetSymbolAddress((void**)&attnl, g_attnl);
    cudaGetSymbolAddress((void**)&xh, g_xh);
    cudaGetSymbolAddress((void**)&xl, g_xl);
    cudaGetSymbolAddress((void**)&ctxh, g_ctxh);
    cudaGetSymbolAddress((void**)&ctxl, g_ctxl);
    cudaGetSymbolAddress((void**)&wf, g_wf);
    cudaGetSymbolAddress((void**)&qkvh, g_qkvh);
    cudaGetSymbolAddress((void**)&qkvl, g_qkvl);

    cudaFuncSetAttribute(tgemm_f16<true>,
                         cudaFuncAttributeMaxDynamicSharedMemorySize, GEMM_SMEM_BT);
    cudaFuncSetAttribute(tgemm_f16<false>,
                         cudaFuncAttributeMaxDynamicSharedMemorySize, GEMM_SMEM_BN);
    cudaFuncSetAttribute(flash_tc,
                         cudaFuncAttributeMaxDynamicSharedMemorySize, FLASH_SMEM);

    const size_t WSZ = (size_t)NTOK * HID;
    const size_t AS  = (size_t)SEQ * NTOK;
    const size_t SZ  = (size_t)SEQ * HID;

    // convert inputs
    cvt_hilo_f16<<<SEQ * HID / 1024, 256>>>(x, xh, xl);
    W8 w8;
    for (int i = 0; i < 8; i++) w8.src[i] = (const float*)d_in[1 + i];
    cvt_w8<<<dim3(WSZ / 1024, 8), 256>>>(w8, wf);

    dim3 gg3(HID / 128, SEQ / 128, 6);   // 3 z * splitK 2
    dim3 gg1(HID / 128, SEQ / 128, 2);   // 1 z * splitK 2

    // ---- QKV pattention GEMM1 (x @ keys^T), batched, split-K=2 ----
    GBF p1 = {};
    for (int z = 0; z < 3; z++) {
        p1.Ah[z] = xh;  p1.Al[z] = xl;
        p1.B[z]  = wf + (size_t)(z * 2) * WSZ;   // qk,kk,vk
        p1.C[z]  = part + z * AS;
    }
    tgemm_f16<true><<<gg3, 256, GEMM_SMEM_BT>>>(p1, SEQ, NTOK, HID);

    gelu_l2norm_cvt<<<3 * SEQ, 256>>>(part, attnh, attnl);

    // ---- GEMM2 (w @ vals), split-K=2 -> reduce+scale+split ----
    GBF p2 = {};
    for (int z = 0; z < 3; z++) {
        p2.Ah[z] = attnh + z * AS;  p2.Al[z] = attnl + z * AS;
        p2.B[z]  = wf + (size_t)(z * 2 + 1) * WSZ;   // qv,kv,vv
        p2.C[z]  = part + z * SZ;
    }
    tgemm_f16<false><<<gg3, 256, GEMM_SMEM_BN>>>(p2, SEQ, HID, NTOK);

    reduce_cvt_qkv<<<dim3(SEQ * HID / 1024, 3), 256>>>(part, qkvh, qkvl);

    // ---- tensor-core causal attention (fp16 2-term) -> ctx fp16 hi/lo ----
    flash_tc<<<dim3(SEQ / 128, NHEAD), 256, FLASH_SMEM>>>(qkvh, qkvl, ctxh, ctxl);

    // ---- output projection, split-K=2 ----
    GBF p3 = {};
    p3.Ah[0] = ctxh; p3.Al[0] = ctxl;
    p3.B[0]  = wf + (size_t)6 * WSZ;   // pk
    p3.C[0]  = part;
    tgemm_f16<true><<<gg1, 256, GEMM_SMEM_BT>>>(p3, SEQ, NTOK, HID);

    gelu_l2norm_cvt<<<SEQ, 256>>>(part, attnh, attnl);

    GBF p4 = {};
    p4.Ah[0] = attnh; p4.Al[0] = attnl;
    p4.B[0]  = wf + (size_t)7 * WSZ;   // pv
    p4.C[0]  = part;
    tgemm_f16<false><<<gg1, 256, GEMM_SMEM_BN>>>(p4, SEQ, HID, NTOK);

    reduce_out<<<SEQ * HID / 1024, 256>>>(part, out);
}

// round 14
// speedup vs baseline: 1.7922x; 1.2301x over previous
#include <cuda_runtime.h>
#include <cuda_bf16.h>
#include <cuda_fp16.h>
#include <mma.h>
#include <math.h>
#include <cstdint>

using namespace nvcuda;

#define SEQ   2048
#define HID   1024
#define NTOK  1024
#define NHEAD 16
#define HDIM  64

typedef __half f16;

#define PART (3 * SEQ * NTOK)   // stride between split-K partial slabs (floats)

// ---------------- scratch (device globals; no runtime allocation) ----------
__device__ float g_part[2 * 3 * SEQ * NTOK];   // split-K partials (48 MB)
__device__ f16 g_attn[3 * SEQ * NTOK];         // gelu out (single fp16, GEMM A)
__device__ f16 g_x16[SEQ * HID];
__device__ f16 g_ctx16[SEQ * HID];
__device__ f16 g_wf[8][NTOK * HID];            // weights, single fp16 (GEMM B)
__device__ f16 g_qkvh[3 * SEQ * HID];          // q hi (scaled) | k | v
__device__ f16 g_qkvl[3 * SEQ * HID];          // q lo          | (unused)

// ---------------- small helpers -------------------------------------------
__device__ __forceinline__ unsigned short f2u(f16 h) {
    return *reinterpret_cast<unsigned short*>(&h);
}
__device__ __forceinline__ unsigned pf2(f16 a, f16 b) {
    return (unsigned)f2u(a) | ((unsigned)f2u(b) << 16);
}
__device__ __forceinline__ void split_f16(float x, f16& h, f16& l) {
    h = __float2half_rn(x);
    l = __float2half_rn(x - __half2float(h));
}
__device__ __forceinline__ void cpa16(void* smem, const void* gmem) {
    unsigned s = (unsigned)__cvta_generic_to_shared(smem);
    asm volatile("cp.async.cg.shared.global [%0], [%1], 16;" :: "r"(s), "l"(gmem));
}
#define CPA_COMMIT() asm volatile("cp.async.commit_group;")
#define CPA_WAIT(n)  asm volatile("cp.async.wait_group %0;" :: "n"(n))

// ---------------- conversions ----------------------------------------------
__global__ void __launch_bounds__(256) cvt_f16(const float* __restrict__ in,
                                               f16* __restrict__ o)
{
    int i = (blockIdx.x * 256 + threadIdx.x) * 4;
    float4 v = *(const float4*)(in + i);
    uint2 u;
    u.x = pf2(__float2half_rn(v.x), __float2half_rn(v.y));
    u.y = pf2(__float2half_rn(v.z), __float2half_rn(v.w));
    *(uint2*)(o + i) = u;
}

struct W8 { const float* src[8]; };

__global__ void __launch_bounds__(256) cvt_w8(W8 s, f16* __restrict__ w)
{
    const size_t WSZ = (size_t)NTOK * HID;
    int z = blockIdx.y;
    int i = (blockIdx.x * 256 + threadIdx.x) * 4;
    float4 v = *(const float4*)(s.src[z] + i);
    uint2 o;
    o.x = pf2(__float2half_rn(v.x), __float2half_rn(v.y));
    o.y = pf2(__float2half_rn(v.z), __float2half_rn(v.w));
    *(uint2*)(w + z * WSZ + i) = o;
}

// split-K partial reduce + scale + fp16 hi/lo split (for flash q/k/v)
__global__ void __launch_bounds__(256) reduce_cvt_qkv(const float* __restrict__ part,
                                                      f16* __restrict__ hi,
                                                      f16* __restrict__ lo)
{
    const size_t SZ = (size_t)SEQ * HID;
    int z = blockIdx.y;
    const float sc = (z == 0) ? 0.125f : 1.f;
    size_t i = (size_t)(blockIdx.x * 256 + threadIdx.x) * 4 + z * SZ;
    float4 a = *(const float4*)(part + i);
    float4 b = *(const float4*)(part + PART + i);
    f16 h0, h1, h2, h3, l0, l1, l2, l3;
    split_f16((a.x + b.x) * sc, h0, l0); split_f16((a.y + b.y) * sc, h1, l1);
    split_f16((a.z + b.z) * sc, h2, l2); split_f16((a.w + b.w) * sc, h3, l3);
    uint2 H; H.x = pf2(h0, h1); H.y = pf2(h2, h3);
    uint2 L; L.x = pf2(l0, l1); L.y = pf2(l2, l3);
    *(uint2*)(hi + i) = H;
    *(uint2*)(lo + i) = L;
}

// split-K partial reduce -> fp32 out (final projection)
__global__ void __launch_bounds__(256) reduce_out(const float* __restrict__ part,
                                                  float* __restrict__ out)
{
    size_t i = (size_t)(blockIdx.x * 256 + threadIdx.x) * 4;
    float4 a = *(const float4*)(part + i);
    float4 b = *(const float4*)(part + PART + i);
    *(float4*)(out + i) = make_float4(a.x + b.x, a.y + b.y, a.z + b.z, a.w + b.w);
}

// ---------------- tensor GEMM (pure fp16, 1 term, split-K=2) ---------------
//  BT=true : B is [N,K] row-major (C = A*B^T)
//  BT=false: B is [K,N] row-major (C = A*B)
//  128x128 tile, BK=32, 256 threads (8 warps 4x2, warp tile 32x64).
struct GBF {
    const f16 *A[3], *B[3];
    float* C[3];
};

#define ASZ 5120                       // 128*40 elems
#define BSZ_BT 5120                    // 128*40 elems
#define BSZ_NBT 4352                   // 32*136 elems
#define GEMM_SMEM_BT  ((2 * ASZ + 2 * BSZ_BT) * 2)    // 40960 bytes
#define GEMM_SMEM_BN  ((2 * ASZ + 2 * BSZ_NBT) * 2)   // 37888 bytes

template <bool BT>
__global__ void __launch_bounds__(256, 2) tgemm_f16(GBF p, int M, int N, int K)
{
    constexpr int BSZ = BT ? BSZ_BT : BSZ_NBT;

    extern __shared__ f16 dyn[];
    f16* As = dyn;                         // [2][ASZ]
    f16* Bs = dyn + 2 * ASZ;               // [2][BSZ]

    const int zi = blockIdx.z >> 1;
    const int ks = blockIdx.z & 1;
    const f16* __restrict__ A = p.A[zi];
    const f16* __restrict__ B = p.B[zi];
    float* __restrict__ C = p.C[zi] + (size_t)ks * PART;

    const int tid = threadIdx.x;
    const int bx = blockIdx.x;
    const int by = blockIdx.y;
    const int wid = tid >> 5;
    const int wm = wid & 3;
    const int wn = wid >> 2;
    const int kbase = ks * (K / 2);

    wmma::fragment<wmma::accumulator, 16, 16, 16, float> cf[2][4];
#pragma unroll
    for (int mi = 0; mi < 2; mi++)
#pragma unroll
        for (int ni = 0; ni < 4; ni++) wmma::fill_fragment(cf[mi][ni], 0.f);

    int arow[2], akq[2], bkr[2], bnq[2];
#pragma unroll
    for (int i = 0; i < 2; i++) {
        int c = tid + i * 256;
        arow[i] = c >> 2;  akq[i] = (c & 3) * 8;
        if (BT) { bkr[i] = c >> 2;  bnq[i] = (c & 3) * 8; }
        else    { bkr[i] = c >> 4;  bnq[i] = (c & 15) * 8; }
    }

    const int T = K / 64;   // half-K in BK=32 tiles

    auto stage = [&](int t, int b) {
        const int kt = kbase + t * 32;
#pragma unroll
        for (int i = 0; i < 2; i++) {
            cpa16(As + b * ASZ + arow[i] * 40 + akq[i],
                  A + (size_t)(by * 128 + arow[i]) * K + kt + akq[i]);
            if (BT) {
                cpa16(Bs + b * BSZ + bkr[i] * 40 + bnq[i],
                      B + (size_t)(bx * 128 + bkr[i]) * K + kt + bnq[i]);
            } else {
                cpa16(Bs + b * BSZ + bkr[i] * 136 + bnq[i],
                      B + (size_t)(kt + bkr[i]) * N + bx * 128 + bnq[i]);
            }
        }
        CPA_COMMIT();
    };

    stage(0, 0);

    for (int t = 0; t < T; t++) {
        const int b = t & 1;
        CPA_WAIT(0);
        __syncthreads();
        if (t + 1 < T) stage(t + 1, b ^ 1);

        const f16* as_p = As + b * ASZ;
        const f16* bs_p = Bs + b * BSZ;

#pragma unroll
        for (int kk = 0; kk < 2; kk++) {
            wmma::fragment<wmma::matrix_a, 16, 16, 16, f16,
                           wmma::row_major> af[2];
#pragma unroll
            for (int mi = 0; mi < 2; mi++)
                wmma::load_matrix_sync(af[mi], as_p + (wm * 32 + mi * 16) * 40 + kk * 16, 40);
            if (BT) {
                wmma::fragment<wmma::matrix_b, 16, 16, 16, f16,
                               wmma::col_major> bfr[4];
#pragma unroll
                for (int ni = 0; ni < 4; ni++)
                    wmma::load_matrix_sync(bfr[ni], bs_p + (wn * 64 + ni * 16) * 40 + kk * 16, 40);
#pragma unroll
                for (int mi = 0; mi < 2; mi++)
#pragma unroll
                    for (int ni = 0; ni < 4; ni++)
                        wmma::mma_sync(cf[mi][ni], af[mi], bfr[ni], cf[mi][ni]);
            } else {
                wmma::fragment<wmma::matrix_b, 16, 16, 16, f16,
                               wmma::row_major> bfr[4];
#pragma unroll
                for (int ni = 0; ni < 4; ni++)
                    wmma::load_matrix_sync(bfr[ni], bs_p + kk * 16 * 136 + wn * 64 + ni * 16, 136);
#pragma unroll
                for (int mi = 0; mi < 2; mi++)
#pragma unroll
                    for (int ni = 0; ni < 4; ni++)
                        wmma::mma_sync(cf[mi][ni], af[mi], bfr[ni], cf[mi][ni]);
            }
        }
    }

#pragma unroll
    for (int mi = 0; mi < 2; mi++)
#pragma unroll
        for (int ni = 0; ni < 4; ni++) {
            float* Cp = C + (size_t)(by * 128 + wm * 32 + mi * 16) * N
                          + bx * 128 + wn * 64 + ni * 16;
            wmma::store_matrix_sync(Cp, cf[mi][ni], N, wmma::mem_row_major);
        }
}

// ---------------- gelu + L2-norm over summed split-K partials -------------
// outputs single fp16 (GEMM A operand)
__global__ void __launch_bounds__(256) gelu_l2norm_cvt(const float* __restrict__ part,
                                                       f16* __restrict__ o)
{
    const int row = blockIdx.x;
    const int tid = threadIdx.x;
    __shared__ float g[NTOK];
    __shared__ float ws[8];

    const float* p0 = part + (size_t)row * NTOK;
    const float* p1 = p0 + PART;

    float ss = 0.f;
    for (int i = tid; i < NTOK; i += 256) {
        float v = p0[i] + p1[i];
        float gv = 0.5f * v * (1.f + erff(v * 0.70710678118654752f));
        g[i] = gv;
        ss += gv * gv;
    }
#pragma unroll
    for (int of = 16; of > 0; of >>= 1) ss += __shfl_xor_sync(0xffffffffu, ss, of);
    if ((tid & 31) == 0) ws[tid >> 5] = ss;
    __syncthreads();

    float tot = 0.f;
#pragma unroll
    for (int w = 0; w < 8; w++) tot += ws[w];

    const float sc = 32.f * rsqrtf(tot);
    for (int i = tid; i < NTOK; i += 256)
        o[(size_t)row * NTOK + i] = __float2half_rn(g[i] * sc);
}

// ---------------- tensor-core causal flash attention (fp16, 2-term) -------
#define FPAD 72
#define SPAD 68

__global__ void __launch_bounds__(256) flash_tc(const f16* __restrict__ qkvh,
                                                const f16* __restrict__ qkvl,
                                                f16* __restrict__ ctx)
{
    const size_t SZ = (size_t)SEQ * HID;
    const int tid  = threadIdx.x;
    const int wid  = tid >> 5;
    const int head = blockIdx.y;
    const int qt   = gridDim.x - 1 - blockIdx.x;   // heavy tiles first
    const int hc   = head * HDIM;

    extern __shared__ char dynb[];
    f16*   Qh  = (f16*)dynb;
    f16*   Ql  = Qh + 128 * FPAD;
    f16*   KVs = Ql + 128 * FPAD;
    float* S   = (float*)(KVs + 2 * 2 * 64 * FPAD);
    float* O   = S + 128 * SPAD;
    f16*   Ph  = (f16*)(O + 128 * SPAD);
    f16*   Pl  = Ph + 128 * FPAD;

    const int myrow  = tid >> 1;
    const int myhalf = tid & 1;
    float m_reg = -1e30f, l_reg = 0.f;

    {
        float* Orow = O + myrow * SPAD + myhalf * 32;
#pragma unroll
        for (int j = 0; j < 32; j += 4)
            *(float4*)(Orow + j) = make_float4(0.f, 0.f, 0.f, 0.f);
    }

    for (int i = tid; i < 1024; i += 256) {
        int r = i >> 3, c8 = (i & 7) * 8;
        size_t g = (size_t)(qt * 128 + r) * HID + hc + c8;
        cpa16(Qh + r * FPAD + c8, qkvh + g);
        cpa16(Ql + r * FPAD + c8, qkvl + g);
    }
    CPA_COMMIT();

    auto stageKV = [&](int step, int buf) {
        const int kb = step * 64;
        f16* base = KVs + buf * (2 * 64 * FPAD);
        for (int i = tid; i < 512; i += 256) {
            int r = i >> 3, c8 = (i & 7) * 8;
            size_t g = (size_t)(kb + r) * HID + hc + c8;
            cpa16(base + 0 * 64 * FPAD + r * FPAD + c8, qkvh + SZ + g);       // K
            cpa16(base + 1 * 64 * FPAD + r * FPAD + c8, qkvh + 2 * SZ + g);   // V
        }
        CPA_COMMIT();
    };

    const int nsteps = 2 * qt + 2;
    stageKV(0, 0);

    const int wq = wid * 16;

    for (int step = 0; step < nsteps; step++) {
        const int buf = step & 1;
        const int kb  = step * 64;
        CPA_WAIT(0);
        __syncthreads();
        if (step + 1 < nsteps) stageKV(step + 1, buf ^ 1);

        const f16* kf = KVs + buf * (2 * 64 * FPAD);
        const f16* vf = kf + 64 * FPAD;

        {
            wmma::fragment<wmma::matrix_a, 16, 16, 16, f16, wmma::row_major> ah[4], al[4];
#pragma unroll
            for (int ks = 0; ks < 4; ks++) {
                wmma::load_matrix_sync(ah[ks], Qh + wq * FPAD + ks * 16, FPAD);
                wmma::load_matrix_sync(al[ks], Ql + wq * FPAD + ks * 16, FPAD);
            }
#pragma unroll
            for (int nf = 0; nf < 4; nf++) {
                wmma::fragment<wmma::accumulator, 16, 16, 16, float> acc;
                wmma::fill_fragment(acc, 0.f);
#pragma unroll
                for (int ks = 0; ks < 4; ks++) {
                    wmma::fragment<wmma::matrix_b, 16, 16, 16, f16, wmma::col_major> bk;
                    wmma::load_matrix_sync(bk, kf + nf * 16 * FPAD + ks * 16, FPAD);
                    wmma::mma_sync(acc, ah[ks], bk, acc);
                    wmma::mma_sync(acc, al[ks], bk, acc);
                }
                wmma::store_matrix_sync(S + wq * SPAD + nf * 16, acc, SPAD,
                                        wmma::mem_row_major);
            }
        }
        __syncthreads();

        {
            const int qrow = qt * 128 + myrow;
            int jmax = qrow - kb + 1;
            if (jmax > 64) jmax = 64;
            const int base = myhalf * 32;
            const float* Srow = S + myrow * SPAD + base;
            unsigned* ph = (unsigned*)(Ph + myrow * FPAD) + myhalf * 16;
            unsigned* pl = (unsigned*)(Pl + myrow * FPAD) + myhalf * 16;

            float lmax = -1e30f;
#pragma unroll
            for (int j = 0; j < 32; j++)
                if (base + j < jmax) lmax = fmaxf(lmax, Srow[j]);
            float omax = __shfl_xor_sync(0xffffffffu, lmax, 1);
            float tmax = fmaxf(lmax, omax);

            const bool active = (jmax > 0);
            float mnew = active ? fmaxf(m_reg, tmax) : m_reg;
            float corr = __expf(m_reg - mnew);

            float suml = 0.f;
#pragma unroll
            for (int j2 = 0; j2 < 16; j2++) {
                int ja = base + 2 * j2;
                float pa = (ja < jmax)     ? __expf(Srow[2 * j2]     - mnew) : 0.f;
                float pb = (ja + 1 < jmax) ? __expf(Srow[2 * j2 + 1] - mnew) : 0.f;
                suml += pa + pb;
                f16 ha, la, hb, lb;
                split_f16(pa, ha, la); split_f16(pb, hb, lb);
                ph[j2] = pf2(ha, hb);
                pl[j2] = pf2(la, lb);
            }
            float osum = __shfl_xor_sync(0xffffffffu, suml, 1);
            l_reg = l_reg * corr + suml + osum;
            m_reg = mnew;

            float* Orow = O + myrow * SPAD + base;
#pragma unroll
            for (int j = 0; j < 32; j += 4) {
                float4 v = *(float4*)(Orow + j);
                *(float4*)(Orow + j) = make_float4(v.x * corr, v.y * corr,
                                                   v.z * corr, v.w * corr);
            }
        }
        __syncthreads();

        {
            wmma::fragment<wmma::matrix_a, 16, 16, 16, f16, wmma::row_major> pah[4], pal[4];
#pragma unroll
            for (int ks = 0; ks < 4; ks++) {
                wmma::load_matrix_sync(pah[ks], Ph + wq * FPAD + ks * 16, FPAD);
                wmma::load_matrix_sync(pal[ks], Pl + wq * FPAD + ks * 16, FPAD);
            }
#pragma unroll
            for (int nf = 0; nf < 4; nf++) {
                wmma::fragment<wmma::accumulator, 16, 16, 16, float> acc;
                wmma::load_matrix_sync(acc, O + wq * SPAD + nf * 16, SPAD,
                                       wmma::mem_row_major);
#pragma unroll
                for (int ks = 0; ks < 4; ks++) {
                    wmma::fragment<wmma::matrix_b, 16, 16, 16, f16, wmma::row_major> bv;
                    wmma::load_matrix_sync(bv, vf + ks * 16 * FPAD + nf * 16, FPAD);
                    wmma::mma_sync(acc, pah[ks], bv, acc);
                    wmma::mma_sync(acc, pal[ks], bv, acc);
                }
                wmma::store_matrix_sync(O + wq * SPAD + nf * 16, acc, SPAD,
                                        wmma::mem_row_major);
            }
        }
    }

    __syncthreads();

    // epilogue: O/l -> ctx single fp16
    {
        const float invl = 1.f / l_reg;
        const float* Orow = O + myrow * SPAD + myhalf * 32;
        size_t gbase = (size_t)(qt * 128 + myrow) * HID + hc + myhalf * 32;
#pragma unroll
        for (int j = 0; j < 32; j++)
            ctx[gbase + j] = __float2half_rn(Orow[j] * invl);
    }
}

#define FLASH_SMEM (2*128*FPAD*2 + 2*2*64*FPAD*2 + 2*128*SPAD*4 + 2*128*FPAD*2 + 128)

// ---------------------------------------------------------------------------
extern "C" void kernel_launch(void* const* d_in, const int* in_sizes, int n_in,
                              void* d_out, int out_size)
{
    const float* x = (const float*)d_in[0];
    float* out = (float*)d_out;

    float* part;
    f16 *attn, *x16, *ctx16, *wf, *qkvh, *qkvl;
    cudaGetSymbolAddress((void**)&part, g_part);
    cudaGetSymbolAddress((void**)&attn, g_attn);
    cudaGetSymbolAddress((void**)&x16, g_x16);
    cudaGetSymbolAddress((void**)&ctx16, g_ctx16);
    cudaGetSymbolAddress((void**)&wf, g_wf);
    cudaGetSymbolAddress((void**)&qkvh, g_qkvh);
    cudaGetSymbolAddress((void**)&qkvl, g_qkvl);

    cudaFuncSetAttribute(tgemm_f16<true>,
                         cudaFuncAttributeMaxDynamicSharedMemorySize, GEMM_SMEM_BT);
    cudaFuncSetAttribute(tgemm_f16<false>,
                         cudaFuncAttributeMaxDynamicSharedMemorySize, GEMM_SMEM_BN);
    cudaFuncSetAttribute(flash_tc,
                         cudaFuncAttributeMaxDynamicSharedMemorySize, FLASH_SMEM);

    const size_t WSZ = (size_t)NTOK * HID;
    const size_t AS  = (size_t)SEQ * NTOK;
    const size_t SZ  = (size_t)SEQ * HID;

    // convert inputs (single fp16)
    cvt_f16<<<SEQ * HID / 1024, 256>>>(x, x16);
    W8 w8;
    for (int i = 0; i < 8; i++) w8.src[i] = (const float*)d_in[1 + i];
    cvt_w8<<<dim3(WSZ / 1024, 8), 256>>>(w8, wf);

    dim3 gg3(HID / 128, SEQ / 128, 6);   // 3 z * splitK 2
    dim3 gg1(HID / 128, SEQ / 128, 2);   // 1 z * splitK 2

    // ---- QKV pattention GEMM1 (x @ keys^T), batched, split-K=2 ----
    GBF p1 = {};
    for (int z = 0; z < 3; z++) {
        p1.A[z] = x16;
        p1.B[z] = wf + (size_t)(z * 2) * WSZ;   // qk,kk,vk
        p1.C[z] = part + z * AS;
    }
    tgemm_f16<true><<<gg3, 256, GEMM_SMEM_BT>>>(p1, SEQ, NTOK, HID);

    gelu_l2norm_cvt<<<3 * SEQ, 256>>>(part, attn);

    // ---- GEMM2 (w @ vals), split-K=2 -> reduce+scale+split ----
    GBF p2 = {};
    for (int z = 0; z < 3; z++) {
        p2.A[z] = attn + z * AS;
        p2.B[z] = wf + (size_t)(z * 2 + 1) * WSZ;   // qv,kv,vv
        p2.C[z] = part + z * SZ;
    }
    tgemm_f16<false><<<gg3, 256, GEMM_SMEM_BN>>>(p2, SEQ, HID, NTOK);

    reduce_cvt_qkv<<<dim3(SEQ * HID / 1024, 3), 256>>>(part, qkvh, qkvl);

    // ---- tensor-core causal attention (fp16 2-term) -> ctx fp16 ----
    flash_tc<<<dim3(SEQ / 128, NHEAD), 256, FLASH_SMEM>>>(qkvh, qkvl, ctx16);

    // ---- output projection, split-K=2 ----
    GBF p3 = {};
    p3.A[0] = ctx16;
    p3.B[0] = wf + (size_t)6 * WSZ;   // pk
    p3.C[0] = part;
    tgemm_f16<true><<<gg1, 256, GEMM_SMEM_BT>>>(p3, SEQ, NTOK, HID);

    gelu_l2norm_cvt<<<SEQ, 256>>>(part, attn);

    GBF p4 = {};
    p4.A[0] = attn;
    p4.B[0] = wf + (size_t)7 * WSZ;   // pv
    p4.C[0] = part;
    tgemm_f16<false><<<gg1, 256, GEMM_SMEM_BN>>>(p4, SEQ, HID, NTOK);

    reduce_out<<<SEQ * HID / 1024, 256>>>(part, out);
}

// round 15
// speedup vs baseline: 1.9287x; 1.0762x over previous
#include <cuda_runtime.h>
#include <cuda_fp16.h>
#include <mma.h>
#include <math.h>
#include <cstdint>

using namespace nvcuda;

#define SEQ   2048
#define HID   1024
#define NTOK  1024
#define NHEAD 16
#define HDIM  64

typedef __half f16;

#define PART (3 * SEQ * NTOK)   // stride between split-K partial slabs (floats)

// ---------------- scratch (device globals; no runtime allocation) ----------
__device__ float g_part[2 * 3 * SEQ * NTOK];   // split-K partials (48 MB)
__device__ f16 g_attn[3 * SEQ * NTOK];         // gelu out (fp16, GEMM A)
__device__ f16 g_x16[SEQ * HID];
__device__ f16 g_ctx16[SEQ * HID];
__device__ f16 g_wf[8][NTOK * HID];            // weights fp16 (GEMM B)
__device__ f16 g_qkv[3 * SEQ * HID];           // q(scaled) | k | v  (fp16)

// ---------------- small helpers -------------------------------------------
__device__ __forceinline__ unsigned short f2u(f16 h) {
    return *reinterpret_cast<unsigned short*>(&h);
}
__device__ __forceinline__ unsigned pf2(f16 a, f16 b) {
    return (unsigned)f2u(a) | ((unsigned)f2u(b) << 16);
}
__device__ __forceinline__ void cpa16(void* smem, const void* gmem) {
    unsigned s = (unsigned)__cvta_generic_to_shared(smem);
    asm volatile("cp.async.cg.shared.global [%0], [%1], 16;" :: "r"(s), "l"(gmem));
}
#define CPA_COMMIT() asm volatile("cp.async.commit_group;")
#define CPA_WAIT(n)  asm volatile("cp.async.wait_group %0;" :: "n"(n))

// ---------------- conversions ----------------------------------------------
__global__ void __launch_bounds__(256) cvt_f16(const float* __restrict__ in,
                                               f16* __restrict__ o)
{
    int i = (blockIdx.x * 256 + threadIdx.x) * 4;
    float4 v = *(const float4*)(in + i);
    uint2 u;
    u.x = pf2(__float2half_rn(v.x), __float2half_rn(v.y));
    u.y = pf2(__float2half_rn(v.z), __float2half_rn(v.w));
    *(uint2*)(o + i) = u;
}

struct W8 { const float* src[8]; };

__global__ void __launch_bounds__(256) cvt_w8(W8 s, f16* __restrict__ w)
{
    const size_t WSZ = (size_t)NTOK * HID;
    int z = blockIdx.y;
    int i = (blockIdx.x * 256 + threadIdx.x) * 4;
    float4 v = *(const float4*)(s.src[z] + i);
    uint2 o;
    o.x = pf2(__float2half_rn(v.x), __float2half_rn(v.y));
    o.y = pf2(__float2half_rn(v.z), __float2half_rn(v.w));
    *(uint2*)(w + z * WSZ + i) = o;
}

// ---------------- tensor GEMM (pure fp16, 1 term) --------------------------
//  BT=true : B is [N,K] row-major (C = A*B^T);  BT=false: B is [K,N]
//  SPLITK : split-K=2, fp32 partials at ks*PART
//  F16OUT : no split-K; scaled fp16 output straight from fragments
//  128x128 tile, BK=32, 256 threads (8 warps 4x2, warp tile 32x64).
struct GBF {
    const f16 *A[3], *B[3];
    float* C[3];
    f16* O[3];
    float scale[3];
};

#define ASZ 5120                       // 128*40 elems
#define BSZ_BT 5120                    // 128*40 elems
#define BSZ_NBT 4352                   // 32*136 elems
#define GEMM_SMEM_BT  ((2 * ASZ + 2 * BSZ_BT) * 2)    // 40960 bytes
#define GEMM_SMEM_BN  ((2 * ASZ + 2 * BSZ_NBT) * 2)   // 37888 bytes

template <bool BT, bool SPLITK, bool F16OUT>
__global__ void __launch_bounds__(256, 2) tgemm_f16(GBF p, int M, int N, int K)
{
    constexpr int BSZ = BT ? BSZ_BT : BSZ_NBT;

    extern __shared__ f16 dyn[];
    f16* As = dyn;                         // [2][ASZ]
    f16* Bs = dyn + 2 * ASZ;               // [2][BSZ]

    const int zi = SPLITK ? (blockIdx.z >> 1) : blockIdx.z;
    const int ks = SPLITK ? (blockIdx.z & 1) : 0;
    const f16* __restrict__ A = p.A[zi];
    const f16* __restrict__ B = p.B[zi];

    const int tid = threadIdx.x;
    const int bx = blockIdx.x;
    const int by = blockIdx.y;
    const int wid = tid >> 5;
    const int wm = wid & 3;
    const int wn = wid >> 2;
    const int kbase = SPLITK ? ks * (K / 2) : 0;

    wmma::fragment<wmma::accumulator, 16, 16, 16, float> cf[2][4];
#pragma unroll
    for (int mi = 0; mi < 2; mi++)
#pragma unroll
        for (int ni = 0; ni < 4; ni++) wmma::fill_fragment(cf[mi][ni], 0.f);

    int arow[2], akq[2], bkr[2], bnq[2];
#pragma unroll
    for (int i = 0; i < 2; i++) {
        int c = tid + i * 256;
        arow[i] = c >> 2;  akq[i] = (c & 3) * 8;
        if (BT) { bkr[i] = c >> 2;  bnq[i] = (c & 3) * 8; }
        else    { bkr[i] = c >> 4;  bnq[i] = (c & 15) * 8; }
    }

    const int T = (SPLITK ? K / 2 : K) / 32;

    auto stage = [&](int t, int b) {
        const int kt = kbase + t * 32;
#pragma unroll
        for (int i = 0; i < 2; i++) {
            cpa16(As + b * ASZ + arow[i] * 40 + akq[i],
                  A + (size_t)(by * 128 + arow[i]) * K + kt + akq[i]);
            if (BT) {
                cpa16(Bs + b * BSZ + bkr[i] * 40 + bnq[i],
                      B + (size_t)(bx * 128 + bkr[i]) * K + kt + bnq[i]);
            } else {
                cpa16(Bs + b * BSZ + bkr[i] * 136 + bnq[i],
                      B + (size_t)(kt + bkr[i]) * N + bx * 128 + bnq[i]);
            }
        }
        CPA_COMMIT();
    };

    stage(0, 0);

    for (int t = 0; t < T; t++) {
        const int b = t & 1;
        CPA_WAIT(0);
        __syncthreads();
        if (t + 1 < T) stage(t + 1, b ^ 1);

        const f16* as_p = As + b * ASZ;
        const f16* bs_p = Bs + b * BSZ;

#pragma unroll
        for (int kk = 0; kk < 2; kk++) {
            wmma::fragment<wmma::matrix_a, 16, 16, 16, f16,
                           wmma::row_major> af[2];
#pragma unroll
            for (int mi = 0; mi < 2; mi++)
                wmma::load_matrix_sync(af[mi], as_p + (wm * 32 + mi * 16) * 40 + kk * 16, 40);
            if (BT) {
                wmma::fragment<wmma::matrix_b, 16, 16, 16, f16,
                               wmma::col_major> bfr[4];
#pragma unroll
                for (int ni = 0; ni < 4; ni++)
                    wmma::load_matrix_sync(bfr[ni], bs_p + (wn * 64 + ni * 16) * 40 + kk * 16, 40);
#pragma unroll
                for (int mi = 0; mi < 2; mi++)
#pragma unroll
                    for (int ni = 0; ni < 4; ni++)
                        wmma::mma_sync(cf[mi][ni], af[mi], bfr[ni], cf[mi][ni]);
            } else {
                wmma::fragment<wmma::matrix_b, 16, 16, 16, f16,
                               wmma::row_major> bfr[4];
#pragma unroll
                for (int ni = 0; ni < 4; ni++)
                    wmma::load_matrix_sync(bfr[ni], bs_p + kk * 16 * 136 + wn * 64 + ni * 16, 136);
#pragma unroll
                for (int mi = 0; mi < 2; mi++)
#pragma unroll
                    for (int ni = 0; ni < 4; ni++)
                        wmma::mma_sync(cf[mi][ni], af[mi], bfr[ni], cf[mi][ni]);
            }
        }
    }

    if (F16OUT) {
        // scaled fp16 output straight from accumulator fragments
        const float sc = p.scale[zi];
        f16* __restrict__ O = p.O[zi];
#pragma unroll
        for (int mi = 0; mi < 2; mi++)
#pragma unroll
            for (int ni = 0; ni < 4; ni++) {
                wmma::fragment<wmma::accumulator, 16, 16, 16, __half> hf;
#pragma unroll
                for (int e = 0; e < hf.num_elements; e++)
                    hf.x[e] = __float2half_rn(cf[mi][ni].x[e] * sc);
                f16* Op = O + (size_t)(by * 128 + wm * 32 + mi * 16) * N
                            + bx * 128 + wn * 64 + ni * 16;
                wmma::store_matrix_sync(Op, hf, N, wmma::mem_row_major);
            }
    } else {
        float* __restrict__ C = p.C[zi] + (SPLITK ? (size_t)ks * PART : 0);
#pragma unroll
        for (int mi = 0; mi < 2; mi++)
#pragma unroll
            for (int ni = 0; ni < 4; ni++) {
                float* Cp = C + (size_t)(by * 128 + wm * 32 + mi * 16) * N
                              + bx * 128 + wn * 64 + ni * 16;
                wmma::store_matrix_sync(Cp, cf[mi][ni], N, wmma::mem_row_major);
            }
    }
}

// ---------------- gelu + L2-norm over summed split-K partials -------------
__global__ void __launch_bounds__(256) gelu_l2norm_cvt(const float* __restrict__ part,
                                                       f16* __restrict__ o)
{
    const int row = blockIdx.x;
    const int tid = threadIdx.x;
    __shared__ float g[NTOK];
    __shared__ float ws[8];

    const float* p0 = part + (size_t)row * NTOK;
    const float* p1 = p0 + PART;

    float ss = 0.f;
    for (int i = tid; i < NTOK; i += 256) {
        float v = p0[i] + p1[i];
        float gv = 0.5f * v * (1.f + erff(v * 0.70710678118654752f));
        g[i] = gv;
        ss += gv * gv;
    }
#pragma unroll
    for (int of = 16; of > 0; of >>= 1) ss += __shfl_xor_sync(0xffffffffu, ss, of);
    if ((tid & 31) == 0) ws[tid >> 5] = ss;
    __syncthreads();

    float tot = 0.f;
#pragma unroll
    for (int w = 0; w < 8; w++) tot += ws[w];

    const float sc = 32.f * rsqrtf(tot);
    for (int i = tid; i < NTOK; i += 256)
        o[(size_t)row * NTOK + i] = __float2half_rn(g[i] * sc);
}

// ---------------- tensor-core causal flash attention (fp16, 1-term) -------
#define FPAD 72
#define SPAD 68

__global__ void __launch_bounds__(256) flash_tc(const f16* __restrict__ qkv,
                                                f16* __restrict__ ctx)
{
    const size_t SZ = (size_t)SEQ * HID;
    const int tid  = threadIdx.x;
    const int wid  = tid >> 5;
    const int head = blockIdx.y;
    const int qt   = gridDim.x - 1 - blockIdx.x;   // heavy tiles first
    const int hc   = head * HDIM;

    extern __shared__ char dynb[];
    f16*   Qs  = (f16*)dynb;                        // [128][72]
    f16*   KVs = Qs + 128 * FPAD;                   // [2 buf][2 arr][64*72]
    float* S   = (float*)(KVs + 2 * 2 * 64 * FPAD); // [128][68]
    float* O   = S + 128 * SPAD;                    // [128][68]
    f16*   Ps  = (f16*)(O + 128 * SPAD);            // [128][72]

    const int myrow  = tid >> 1;
    const int myhalf = tid & 1;
    float m_reg = -1e30f, l_reg = 0.f;

    {
        float* Orow = O + myrow * SPAD + myhalf * 32;
#pragma unroll
        for (int j = 0; j < 32; j += 4)
            *(float4*)(Orow + j) = make_float4(0.f, 0.f, 0.f, 0.f);
    }

    for (int i = tid; i < 1024; i += 256) {
        int r = i >> 3, c8 = (i & 7) * 8;
        cpa16(Qs + r * FPAD + c8, qkv + (size_t)(qt * 128 + r) * HID + hc + c8);
    }
    CPA_COMMIT();

    auto stageKV = [&](int step, int buf) {
        const int kb = step * 64;
        f16* base = KVs + buf * (2 * 64 * FPAD);
        for (int i = tid; i < 512; i += 256) {
            int r = i >> 3, c8 = (i & 7) * 8;
            size_t g = (size_t)(kb + r) * HID + hc + c8;
            cpa16(base + 0 * 64 * FPAD + r * FPAD + c8, qkv + SZ + g);       // K
            cpa16(base + 1 * 64 * FPAD + r * FPAD + c8, qkv + 2 * SZ + g);   // V
        }
        CPA_COMMIT();
    };

    const int nsteps = 2 * qt + 2;
    stageKV(0, 0);

    const int wq = wid * 16;

    for (int step = 0; step < nsteps; step++) {
        const int buf = step & 1;
        const int kb  = step * 64;
        CPA_WAIT(0);
        __syncthreads();
        if (step + 1 < nsteps) stageKV(step + 1, buf ^ 1);

        const f16* kf = KVs + buf * (2 * 64 * FPAD);
        const f16* vf = kf + 64 * FPAD;

        // ---- QK^T -> S[128][64] ----
        {
            wmma::fragment<wmma::matrix_a, 16, 16, 16, f16, wmma::row_major> qa[4];
#pragma unroll
            for (int ks = 0; ks < 4; ks++)
                wmma::load_matrix_sync(qa[ks], Qs + wq * FPAD + ks * 16, FPAD);
#pragma unroll
            for (int nf = 0; nf < 4; nf++) {
                wmma::fragment<wmma::accumulator, 16, 16, 16, float> acc;
                wmma::fill_fragment(acc, 0.f);
#pragma unroll
                for (int ks = 0; ks < 4; ks++) {
                    wmma::fragment<wmma::matrix_b, 16, 16, 16, f16, wmma::col_major> bk;
                    wmma::load_matrix_sync(bk, kf + nf * 16 * FPAD + ks * 16, FPAD);
                    wmma::mma_sync(acc, qa[ks], bk, acc);
                }
                wmma::store_matrix_sync(S + wq * SPAD + nf * 16, acc, SPAD,
                                        wmma::mem_row_major);
            }
        }
        __syncthreads();

        // ---- online softmax: 2 threads per row ----
        {
            const int qrow = qt * 128 + myrow;
            int jmax = qrow - kb + 1;
            if (jmax > 64) jmax = 64;
            const int base = myhalf * 32;
            const float* Srow = S + myrow * SPAD + base;
            unsigned* pp = (unsigned*)(Ps + myrow * FPAD) + myhalf * 16;

            float lmax = -1e30f;
#pragma unroll
            for (int j = 0; j < 32; j++)
                if (base + j < jmax) lmax = fmaxf(lmax, Srow[j]);
            float omax = __shfl_xor_sync(0xffffffffu, lmax, 1);
            float tmax = fmaxf(lmax, omax);

            const bool active = (jmax > 0);
            float mnew = active ? fmaxf(m_reg, tmax) : m_reg;
            float corr = __expf(m_reg - mnew);

            float suml = 0.f;
#pragma unroll
            for (int j2 = 0; j2 < 16; j2++) {
                int ja = base + 2 * j2;
                float pa = (ja < jmax)     ? __expf(Srow[2 * j2]     - mnew) : 0.f;
                float pb = (ja + 1 < jmax) ? __expf(Srow[2 * j2 + 1] - mnew) : 0.f;
                suml += pa + pb;
                pp[j2] = pf2(__float2half_rn(pa), __float2half_rn(pb));
            }
            float osum = __shfl_xor_sync(0xffffffffu, suml, 1);
            l_reg = l_reg * corr + suml + osum;
            m_reg = mnew;

            float* Orow = O + myrow * SPAD + base;
#pragma unroll
            for (int j = 0; j < 32; j += 4) {
                float4 v = *(float4*)(Orow + j);
                *(float4*)(Orow + j) = make_float4(v.x * corr, v.y * corr,
                                                   v.z * corr, v.w * corr);
            }
        }
        __syncthreads();

        // ---- P*V accumulated into O ----
        {
            wmma::fragment<wmma::matrix_a, 16, 16, 16, f16, wmma::row_major> pa[4];
#pragma unroll
            for (int ks = 0; ks < 4; ks++)
                wmma::load_matrix_sync(pa[ks], Ps + wq * FPAD + ks * 16, FPAD);
#pragma unroll
            for (int nf = 0; nf < 4; nf++) {
                wmma::fragment<wmma::accumulator, 16, 16, 16, float> acc;
                wmma::load_matrix_sync(acc, O + wq * SPAD + nf * 16, SPAD,
                                       wmma::mem_row_major);
#pragma unroll
                for (int ks = 0; ks < 4; ks++) {
                    wmma::fragment<wmma::matrix_b, 16, 16, 16, f16, wmma::row_major> bv;
                    wmma::load_matrix_sync(bv, vf + ks * 16 * FPAD + nf * 16, FPAD);
                    wmma::mma_sync(acc, pa[ks], bv, acc);
                }
                wmma::store_matrix_sync(O + wq * SPAD + nf * 16, acc, SPAD,
                                        wmma::mem_row_major);
            }
        }
    }

    __syncthreads();

    // epilogue: O/l -> ctx fp16
    {
        const float invl = 1.f / l_reg;
        const float* Orow = O + myrow * SPAD + myhalf * 32;
        size_t gbase = (size_t)(qt * 128 + myrow) * HID + hc + myhalf * 32;
#pragma unroll
        for (int j = 0; j < 32; j++)
            ctx[gbase + j] = __float2half_rn(Orow[j] * invl);
    }
}

#define FLASH_SMEM (128*FPAD*2 + 2*2*64*FPAD*2 + 2*128*SPAD*4 + 128*FPAD*2 + 128)

// ---------------------------------------------------------------------------
extern "C" void kernel_launch(void* const* d_in, const int* in_sizes, int n_in,
                              void* d_out, int out_size)
{
    const float* x = (const float*)d_in[0];
    float* out = (float*)d_out;

    float* part;
    f16 *attn, *x16, *ctx16, *wf, *qkv;
    cudaGetSymbolAddress((void**)&part, g_part);
    cudaGetSymbolAddress((void**)&attn, g_attn);
    cudaGetSymbolAddress((void**)&x16, g_x16);
    cudaGetSymbolAddress((void**)&ctx16, g_ctx16);
    cudaGetSymbolAddress((void**)&wf, g_wf);
    cudaGetSymbolAddress((void**)&qkv, g_qkv);

    cudaFuncSetAttribute(tgemm_f16<true, true, false>,
                         cudaFuncAttributeMaxDynamicSharedMemorySize, GEMM_SMEM_BT);
    cudaFuncSetAttribute(tgemm_f16<false, false, true>,
                         cudaFuncAttributeMaxDynamicSharedMemorySize, GEMM_SMEM_BN);
    cudaFuncSetAttribute(tgemm_f16<false, false, false>,
                         cudaFuncAttributeMaxDynamicSharedMemorySize, GEMM_SMEM_BN);
    cudaFuncSetAttribute(flash_tc,
                         cudaFuncAttributeMaxDynamicSharedMemorySize, FLASH_SMEM);

    const size_t WSZ = (size_t)NTOK * HID;
    const size_t AS  = (size_t)SEQ * NTOK;
    const size_t SZ  = (size_t)SEQ * HID;

    // convert inputs (single fp16)
    cvt_f16<<<SEQ * HID / 1024, 256>>>(x, x16);
    W8 w8;
    for (int i = 0; i < 8; i++) w8.src[i] = (const float*)d_in[1 + i];
    cvt_w8<<<dim3(WSZ / 1024, 8), 256>>>(w8, wf);

    // ---- QKV pattention GEMM1 (x @ keys^T), batched, split-K=2 ----
    GBF p1 = {};
    for (int z = 0; z < 3; z++) {
        p1.A[z] = x16;
        p1.B[z] = wf + (size_t)(z * 2) * WSZ;   // qk,kk,vk
        p1.C[z] = part + z * AS;
    }
    tgemm_f16<true, true, false><<<dim3(8, 16, 6), 256, GEMM_SMEM_BT>>>(p1, SEQ, NTOK, HID);

    gelu_l2norm_cvt<<<3 * SEQ, 256>>>(part, attn);

    // ---- GEMM2 (w @ vals), fused scaled-fp16 epilogue -> qkv ----
    GBF p2 = {};
    for (int z = 0; z < 3; z++) {
        p2.A[z] = attn + z * AS;
        p2.B[z] = wf + (size_t)(z * 2 + 1) * WSZ;   // qv,kv,vv
        p2.O[z] = qkv + z * SZ;
        p2.scale[z] = (z == 0) ? 0.125f : 1.f;
    }
    tgemm_f16<false, false, true><<<dim3(8, 16, 3), 256, GEMM_SMEM_BN>>>(p2, SEQ, HID, NTOK);

    // ---- tensor-core causal attention (fp16 1-term) -> ctx fp16 ----
    flash_tc<<<dim3(SEQ / 128, NHEAD), 256, FLASH_SMEM>>>(qkv, ctx16);

    // ---- output projection: GEMM3 split-K -> gelu -> GEMM4 direct ----
    GBF p3 = {};
    p3.A[0] = ctx16;
    p3.B[0] = wf + (size_t)6 * WSZ;   // pk
    p3.C[0] = part;
    tgemm_f16<true, true, false><<<dim3(8, 16, 2), 256, GEMM_SMEM_BT>>>(p3, SEQ, NTOK, HID);

    gelu_l2norm_cvt<<<SEQ, 256>>>(part, attn);

    GBF p4 = {};
    p4.A[0] = attn;
    p4.B[0] = wf + (size_t)7 * WSZ;   // pv
    p4.C[0] = out;
    tgemm_f16<false, false, false><<<dim3(8, 16, 1), 256, GEMM_SMEM_BN>>>(p4, SEQ, HID, NTOK);
}